// round 4
// baseline (speedup 1.0000x reference)
#include <cuda_runtime.h>
#include <cstdint>

// Problem dims (fixed)
#define Bq   8
#define Tq   2048
#define Cq   1024
#define HIDq 4096
#define Mq   (Bq*Tq)        // 16384 rows
#define NCH  32             // WKV chunks
#define LCH  (Tq/NCH)       // 64 steps per chunk

// GEMM tiling: CTA tile 256x128, warp tile 64x64, BK=32 floats (128B rows)
#define BM     256
#define BN     128
#define BKK    32
#define STAGES 3
#define ASTGB  (BM*BKK*4)            // 32768 bytes per A stage
#define BSTGB  (BN*BKK*4)            // 16384 bytes per B stage
#define STGB   (ASTGB + BSTGB)       // 49152 bytes per stage
#define GEMM_SMEM (STAGES*STGB + 1024)

// ---------------- scratch (static device globals; no allocation) ----------
__device__ float g_xk[(size_t)Mq*Cq];
__device__ float g_xv[(size_t)Mq*Cq];
__device__ float g_xr[(size_t)Mq*Cq];
__device__ float g_k [(size_t)Mq*Cq];
__device__ float g_v [(size_t)Mq*Cq];
__device__ float g_sr[(size_t)Mq*Cq];
__device__ float g_rw[(size_t)Mq*Cq];
__device__ float g_x1[(size_t)Mq*Cq];
__device__ float g_fk[(size_t)Mq*Cq];
__device__ float g_fr[(size_t)Mq*Cq];
__device__ float g_sg[(size_t)Mq*Cq];
__device__ float g_kk[(size_t)Mq*HIDq];
__device__ float g_Ca[(size_t)NCH*Bq*Cq];
__device__ float g_Cb[(size_t)NCH*Bq*Cq];
__device__ float g_Sa[(size_t)NCH*Bq*Cq];
__device__ float g_Sb[(size_t)NCH*Bq*Cq];
// rounded weight copies: Wk,Wv,Wr,Wo,Fr (C*C each) then Fk,Fv (HID*C each)
__device__ float g_wt[(size_t)5*Cq*Cq + (size_t)2*HIDq*Cq];

// ---------------- helpers --------------------------------------------------
__device__ __forceinline__ uint32_t f2tf(float x) {
    uint32_t r;
    asm("cvt.rna.tf32.f32 %0, %1;" : "=r"(r) : "f"(x));
    return r;
}
__device__ __forceinline__ float rtf(float x) { return __uint_as_float(f2tf(x)); }

__device__ __forceinline__ void mma_tf32(float* c, const uint32_t* a, const uint32_t* b) {
    asm volatile(
        "mma.sync.aligned.m16n8k8.row.col.f32.tf32.tf32.f32 "
        "{%0,%1,%2,%3}, {%4,%5,%6,%7}, {%8,%9}, {%0,%1,%2,%3};"
        : "+f"(c[0]), "+f"(c[1]), "+f"(c[2]), "+f"(c[3])
        : "r"(a[0]), "r"(a[1]), "r"(a[2]), "r"(a[3]), "r"(b[0]), "r"(b[1]));
}

__device__ __forceinline__ uint32_t smem_u32(const void* p) {
    uint32_t a;
    asm("{ .reg .u64 t; cvta.to.shared.u64 t, %1; cvt.u32.u64 %0, t; }" : "=r"(a) : "l"(p));
    return a;
}
__device__ __forceinline__ void cp16(uint32_t dst, const float* src) {
    asm volatile("cp.async.cg.shared.global [%0], [%1], 16;" :: "r"(dst), "l"(src));
}
__device__ __forceinline__ void cp_commit() { asm volatile("cp.async.commit_group;"); }
template<int N> __device__ __forceinline__ void cp_wait() {
    asm volatile("cp.async.wait_group %0;" :: "n"(N));
}

// block-wide reduce of 4 values (256 threads)
__device__ __forceinline__ void bred4(float& a, float& b, float& c, float& d) {
    #pragma unroll
    for (int o = 16; o; o >>= 1) {
        a += __shfl_xor_sync(0xffffffffu, a, o);
        b += __shfl_xor_sync(0xffffffffu, b, o);
        c += __shfl_xor_sync(0xffffffffu, c, o);
        d += __shfl_xor_sync(0xffffffffu, d, o);
    }
    __shared__ float sm[8][4];
    int w = threadIdx.x >> 5, l = threadIdx.x & 31;
    if (l == 0) { sm[w][0] = a; sm[w][1] = b; sm[w][2] = c; sm[w][3] = d; }
    __syncthreads();
    a = b = c = d = 0.f;
    #pragma unroll
    for (int j = 0; j < 8; j++) { a += sm[j][0]; b += sm[j][1]; c += sm[j][2]; d += sm[j][3]; }
}

// ---------------- weight rounding (RNE to tf32, stored as fp32) ------------
__global__ __launch_bounds__(256) void round_copy4(const float* __restrict__ src,
                                                   float* __restrict__ dst, int n4)
{
    const int i = blockIdx.x * blockDim.x + threadIdx.x;
    if (i >= n4) return;
    float4 v = reinterpret_cast<const float4*>(src)[i];
    v.x = rtf(v.x); v.y = rtf(v.y); v.z = rtf(v.z); v.w = rtf(v.w);
    reinterpret_cast<float4*>(dst)[i] = v;
}

// ---------------- fused LayerNorm + time-shift + token-mix -----------------
template<int NOUT>
__global__ __launch_bounds__(256) void ln_mix(
    const float* __restrict__ x, const float* __restrict__ g, const float* __restrict__ be,
    const float* __restrict__ m0, const float* __restrict__ m1, const float* __restrict__ m2,
    float* __restrict__ o0, float* __restrict__ o1, float* __restrict__ o2)
{
    const int row = blockIdx.x;          // b*T + t
    const int t   = row & (Tq - 1);
    const int i   = threadIdx.x;         // one float4 per thread (C/4 = 256)

    const float4 v = reinterpret_cast<const float4*>(x + (size_t)row * Cq)[i];
    float4 u = make_float4(0.f, 0.f, 0.f, 0.f);
    if (t > 0) u = reinterpret_cast<const float4*>(x + (size_t)(row - 1) * Cq)[i];

    float s  = v.x + v.y + v.z + v.w;
    float ss = v.x*v.x + v.y*v.y + v.z*v.z + v.w*v.w;
    float sp = u.x + u.y + u.z + u.w;
    float sq = u.x*u.x + u.y*u.y + u.z*u.z + u.w*u.w;
    bred4(s, ss, sp, sq);

    const float inv = 1.f / (float)Cq;
    const float mC = s * inv;
    const float rs = rsqrtf(ss * inv - mC * mC + 1e-5f);
    const float mP = sp * inv;
    const float rp = rsqrtf(sq * inv - mP * mP + 1e-5f);

    const float4 g4 = reinterpret_cast<const float4*>(g)[i];
    const float4 b4 = reinterpret_cast<const float4*>(be)[i];

    float xa[4], xx[4];
    const float* vv = &v.x; const float* uu = &u.x;
    const float* gg = &g4.x; const float* bb = &b4.x;
    #pragma unroll
    for (int j = 0; j < 4; j++) {
        xa[j] = (vv[j] - mC) * rs * gg[j] + bb[j];
        xx[j] = (t > 0) ? ((uu[j] - mP) * rp * gg[j] + bb[j]) : 0.f;
    }

    const size_t oi = (size_t)row * (Cq / 4) + i;
    {
        const float4 w4 = reinterpret_cast<const float4*>(m0)[i];
        const float* ww = &w4.x; float4 r; float* rr = &r.x;
        #pragma unroll
        for (int j = 0; j < 4; j++) rr[j] = rtf(xa[j] * ww[j] + xx[j] * (1.f - ww[j]));
        reinterpret_cast<float4*>(o0)[oi] = r;
    }
    {
        const float4 w4 = reinterpret_cast<const float4*>(m1)[i];
        const float* ww = &w4.x; float4 r; float* rr = &r.x;
        #pragma unroll
        for (int j = 0; j < 4; j++) rr[j] = rtf(xa[j] * ww[j] + xx[j] * (1.f - ww[j]));
        reinterpret_cast<float4*>(o1)[oi] = r;
    }
    if (NOUT == 3) {
        const float4 w4 = reinterpret_cast<const float4*>(m2)[i];
        const float* ww = &w4.x; float4 r; float* rr = &r.x;
        #pragma unroll
        for (int j = 0; j < 4; j++) rr[j] = rtf(xa[j] * ww[j] + xx[j] * (1.f - ww[j]));
        reinterpret_cast<float4*>(o2)[oi] = r;
    }
}

// ---------------- tf32 GEMM, 256x128 tile, warp 64x64, cp.async 3 stages ----
// out[m,n] = sum_k A[m,k]*W[n,k]. A,W pre-rounded to tf32 values.
// Smem: XOR-swizzled 128B rows (conflict-free, no padding).
// EPI: 0 none | 1 sigmoid | 2 relu^2 (tf32-rounded) | 3 aux1+acc | 4 aux1+aux2*acc

__device__ __forceinline__ void fill_tile(uint32_t sbase, int stage,
    const float* __restrict__ Ag, const float* __restrict__ Wg, int K, int k0, int tid)
{
    const uint32_t sa = sbase + (uint32_t)stage * STGB;
    #pragma unroll
    for (int p = 0; p < 8; p++) {            // A: 256 rows x 8 chunks = 2048
        const int id  = tid + p * 256;
        const int row = id >> 3, c = id & 7;
        const uint32_t off = (uint32_t)(row * 128 + c * 16);
        cp16(sa + (off ^ ((off >> 3) & 0x70)), Ag + (size_t)row * K + k0 + c * 4);
    }
    const uint32_t sb = sa + ASTGB;
    #pragma unroll
    for (int p = 0; p < 4; p++) {            // B: 128 rows x 8 chunks = 1024
        const int id  = tid + p * 256;
        const int row = id >> 3, c = id & 7;
        const uint32_t off = (uint32_t)(row * 128 + c * 16);
        cp16(sb + (off ^ ((off >> 3) & 0x70)), Wg + (size_t)row * K + k0 + c * 4);
    }
}

// swizzled float index within a tile: row*32 floats, col in floats
__device__ __forceinline__ int swidx(int row, int col) {
    return row * 32 + (col ^ ((row & 7) * 4));
}

template<int EPI>
__device__ __forceinline__ void epi_store(float* __restrict__ out, size_t idx,
    float c0, float c1, const float* __restrict__ a1, const float* __restrict__ a2)
{
    if (EPI == 1) { c0 = 1.f / (1.f + __expf(-c0)); c1 = 1.f / (1.f + __expf(-c1)); }
    else if (EPI == 2) {
        c0 = fmaxf(c0, 0.f); c0 = rtf(c0 * c0);
        c1 = fmaxf(c1, 0.f); c1 = rtf(c1 * c1);
    }
    else if (EPI == 3) { c0 += a1[idx]; c1 += a1[idx + 1]; }
    else if (EPI == 4) { c0 = a1[idx] + a2[idx] * c0; c1 = a1[idx + 1] + a2[idx + 1] * c1; }
    float2 t; t.x = c0; t.y = c1;
    *reinterpret_cast<float2*>(out + idx) = t;
}

template<int EPI>
__global__ __launch_bounds__(256, 1) void gemm_tf32(
    const float* __restrict__ A, const float* __restrict__ W, float* __restrict__ out,
    const float* __restrict__ aux1, const float* __restrict__ aux2, int N, int K)
{
    extern __shared__ float dsm[];
    const uint32_t sbase = (smem_u32(dsm) + 1023u) & ~1023u;
    float* smf = (float*)((char*)dsm + (sbase - smem_u32(dsm)));

    const int tid  = threadIdx.x;
    const int lane = tid & 31;
    const int warp = tid >> 5;
    const int wm   = warp >> 1;   // 0..3 -> 64 rows each
    const int wn   = warp & 1;    // 0..1 -> 64 cols each

    const int brow = blockIdx.y * BM;
    const int bcol = blockIdx.x * BN;
    const float* Ag = A + (size_t)brow * K;
    const float* Wg = W + (size_t)bcol * K;
    const int ntiles = K / BKK;

    // prologue
    fill_tile(sbase, 0, Ag, Wg, K, 0,   tid); cp_commit();
    fill_tile(sbase, 1, Ag, Wg, K, BKK, tid); cp_commit();

    float acc[4][8][4];
    #pragma unroll
    for (int mt = 0; mt < 4; mt++)
        #pragma unroll
        for (int nt = 0; nt < 8; nt++)
            #pragma unroll
            for (int q = 0; q < 4; q++) acc[mt][nt][q] = 0.f;

    const int qrow = lane >> 2;     // 0..7
    const int qcol = lane & 3;      // 0..3

    for (int t = 0; t < ntiles; t++) {
        cp_wait<STAGES - 2>();
        __syncthreads();

        const int tp = t + STAGES - 1;
        if (tp < ntiles) fill_tile(sbase, tp % STAGES, Ag, Wg, K, tp * BKK, tid);
        cp_commit();

        const uint32_t* a_s = reinterpret_cast<const uint32_t*>(smf + (size_t)(t % STAGES) * (STGB / 4));
        const uint32_t* b_s = a_s + (ASTGB / 4);

        #pragma unroll
        for (int ks = 0; ks < 4; ks++) {
            const int k8 = ks * 8;
            uint32_t a[4][4], b[8][2];
            #pragma unroll
            for (int mt = 0; mt < 4; mt++) {
                const int r0 = wm * 64 + mt * 16 + qrow;
                a[mt][0] = a_s[swidx(r0,     k8 + qcol)];
                a[mt][1] = a_s[swidx(r0 + 8, k8 + qcol)];
                a[mt][2] = a_s[swidx(r0,     k8 + 4 + qcol)];
                a[mt][3] = a_s[swidx(r0 + 8, k8 + 4 + qcol)];
            }
            #pragma unroll
            for (int nt = 0; nt < 8; nt++) {
                const int c0 = wn * 64 + nt * 8 + qrow;
                b[nt][0] = b_s[swidx(c0, k8 + qcol)];
                b[nt][1] = b_s[swidx(c0, k8 + 4 + qcol)];
            }
            #pragma unroll
            for (int mt = 0; mt < 4; mt++)
                #pragma unroll
                for (int nt = 0; nt < 8; nt++)
                    mma_tf32(acc[mt][nt], a[mt], b[nt]);
        }
        __syncthreads();
    }

    // epilogue straight from registers
    #pragma unroll
    for (int mt = 0; mt < 4; mt++) {
        #pragma unroll
        for (int nt = 0; nt < 8; nt++) {
            const int row = brow + wm * 64 + mt * 16 + qrow;
            const int col = bcol + wn * 64 + nt * 8 + qcol * 2;
            const size_t i0 = (size_t)row * N + col;
            const size_t i1 = (size_t)(row + 8) * N + col;
            epi_store<EPI>(out, i0, acc[mt][nt][0], acc[mt][nt][1], aux1, aux2);
            epi_store<EPI>(out, i1, acc[mt][nt][2], acc[mt][nt][3], aux1, aux2);
        }
    }
}

// ---------------- WKV chunked scan ------------------------------------------
__global__ __launch_bounds__(256) void wkv_phase_a(
    const float* __restrict__ k, const float* __restrict__ v,
    const float* __restrict__ td, float* __restrict__ Ca, float* __restrict__ Cb)
{
    const int gid = blockIdx.x * blockDim.x + threadIdx.x;   // < NCH*B*C
    const int c  = gid & (Cq - 1);
    const int r  = gid >> 10;
    const int b  = r & (Bq - 1);
    const int ch = r >> 3;
    const float w  = -expf(td[c]);
    const float dw = expf(w);
    const size_t base = ((size_t)(b * Tq + ch * LCH)) * Cq + c;
    float sa = 0.f, sb = 0.f;
    #pragma unroll 4
    for (int i = 0; i < LCH; i++) {
        const float kt = k[base + (size_t)i * Cq];
        const float vt = v[base + (size_t)i * Cq];
        const float ek = __expf(kt);
        sa = fmaf(dw, sa, ek * vt);
        sb = fmaf(dw, sb, ek);
    }
    Ca[gid] = sa; Cb[gid] = sb;
}

__global__ __launch_bounds__(256) void wkv_scan(
    const float* __restrict__ td,
    const float* __restrict__ Ca, const float* __restrict__ Cb,
    float* __restrict__ Sa, float* __restrict__ Sb)
{
    const int sid = blockIdx.x * blockDim.x + threadIdx.x;   // < B*C
    const int c = sid & (Cq - 1);
    const float w  = -expf(td[c]);
    const float dL = expf((float)LCH * w);
    float sa = 0.f, sb = 0.f;
    #pragma unroll
    for (int ch = 0; ch < NCH; ch++) {
        const int idx = ch * (Bq * Cq) + sid;
        Sa[idx] = sa; Sb[idx] = sb;
        sa = fmaf(dL, sa, Ca[idx]);
        sb = fmaf(dL, sb, Cb[idx]);
    }
}

__global__ __launch_bounds__(256) void wkv_phase_b(
    const float* __restrict__ k, const float* __restrict__ v, const float* __restrict__ sr,
    const float* __restrict__ td, const float* __restrict__ tf,
    const float* __restrict__ Sa, const float* __restrict__ Sb, float* __restrict__ out)
{
    const int gid = blockIdx.x * blockDim.x + threadIdx.x;
    const int c  = gid & (Cq - 1);
    const int r  = gid >> 10;
    const int b  = r & (Bq - 1);
    const int ch = r >> 3;
    const float w  = -expf(td[c]);
    const float dw = expf(w);
    const float eu = expf(tf[c]);
    float a = Sa[gid], bb = Sb[gid];
    const size_t base = ((size_t)(b * Tq + ch * LCH)) * Cq + c;
    #pragma unroll 4
    for (int i = 0; i < LCH; i++) {
        const size_t off = base + (size_t)i * Cq;
        const float kt = k[off];
        const float vt = v[off];
        const float ek = __expf(kt);
        const float euk = eu * ek;
        const float y = (a + euk * vt) / (bb + euk);
        out[off] = rtf(sr[off] * y);          // feeds Wo GEMM only
        a  = fmaf(dw, a,  ek * vt);
        bb = fmaf(dw, bb, ek);
    }
}

// ---------------- launch -----------------------------------------------------
extern "C" void kernel_launch(void* const* d_in, const int* in_sizes, int n_in,
                              void* d_out, int out_size)
{
    const float* x     = (const float*)d_in[0];
    const float* ln1_g = (const float*)d_in[1];
    const float* ln1_b = (const float*)d_in[2];
    const float* ln2_g = (const float*)d_in[3];
    const float* ln2_b = (const float*)d_in[4];
    const float* td    = (const float*)d_in[5];
    const float* tf    = (const float*)d_in[6];
    const float* tmk   = (const float*)d_in[7];
    const float* tmv   = (const float*)d_in[8];
    const float* tmr   = (const float*)d_in[9];
    const float* Wk    = (const float*)d_in[10];
    const float* Wv    = (const float*)d_in[11];
    const float* Wr    = (const float*)d_in[12];
    const float* Wo    = (const float*)d_in[13];
    const float* fmk   = (const float*)d_in[14];
    const float* fmr   = (const float*)d_in[15];
    const float* Fk    = (const float*)d_in[16];
    const float* Fr    = (const float*)d_in[17];
    const float* Fv    = (const float*)d_in[18];
    float* out = (float*)d_out;

    float *xk, *xv, *xr, *k, *v, *sr, *rw, *x1, *fk, *fr, *sg, *kk, *Ca, *Cb, *Sa, *Sb, *wt;
    cudaGetSymbolAddress((void**)&xk, g_xk);
    cudaGetSymbolAddress((void**)&xv, g_xv);
    cudaGetSymbolAddress((void**)&xr, g_xr);
    cudaGetSymbolAddress((void**)&k,  g_k);
    cudaGetSymbolAddress((void**)&v,  g_v);
    cudaGetSymbolAddress((void**)&sr, g_sr);
    cudaGetSymbolAddress((void**)&rw, g_rw);
    cudaGetSymbolAddress((void**)&x1, g_x1);
    cudaGetSymbolAddress((void**)&fk, g_fk);
    cudaGetSymbolAddress((void**)&fr, g_fr);
    cudaGetSymbolAddress((void**)&sg, g_sg);
    cudaGetSymbolAddress((void**)&kk, g_kk);
    cudaGetSymbolAddress((void**)&Ca, g_Ca);
    cudaGetSymbolAddress((void**)&Cb, g_Cb);
    cudaGetSymbolAddress((void**)&Sa, g_Sa);
    cudaGetSymbolAddress((void**)&Sb, g_Sb);
    cudaGetSymbolAddress((void**)&wt, g_wt);

    const size_t CC = (size_t)Cq * Cq;          // 1M
    const size_t HC = (size_t)HIDq * Cq;        // 4M
    float* rWk = wt;
    float* rWv = wt + CC;
    float* rWr = wt + 2 * CC;
    float* rWo = wt + 3 * CC;
    float* rFr = wt + 4 * CC;
    float* rFk = wt + 5 * CC;
    float* rFv = wt + 5 * CC + HC;

    cudaFuncSetAttribute(gemm_tf32<0>, cudaFuncAttributeMaxDynamicSharedMemorySize, GEMM_SMEM);
    cudaFuncSetAttribute(gemm_tf32<1>, cudaFuncAttributeMaxDynamicSharedMemorySize, GEMM_SMEM);
    cudaFuncSetAttribute(gemm_tf32<2>, cudaFuncAttributeMaxDynamicSharedMemorySize, GEMM_SMEM);
    cudaFuncSetAttribute(gemm_tf32<3>, cudaFuncAttributeMaxDynamicSharedMemorySize, GEMM_SMEM);
    cudaFuncSetAttribute(gemm_tf32<4>, cudaFuncAttributeMaxDynamicSharedMemorySize, GEMM_SMEM);

    // round weights (RNE->tf32) into scratch
    round_copy4<<<(int)(CC / 4 + 255) / 256, 256>>>(Wk, rWk, (int)(CC / 4));
    round_copy4<<<(int)(CC / 4 + 255) / 256, 256>>>(Wv, rWv, (int)(CC / 4));
    round_copy4<<<(int)(CC / 4 + 255) / 256, 256>>>(Wr, rWr, (int)(CC / 4));
    round_copy4<<<(int)(CC / 4 + 255) / 256, 256>>>(Wo, rWo, (int)(CC / 4));
    round_copy4<<<(int)(CC / 4 + 255) / 256, 256>>>(Fr, rFr, (int)(CC / 4));
    round_cop4:;
    round_copy4<<<(int)(HC / 4 + 255) / 256, 256>>>(Fk, rFk, (int)(HC / 4));
    round_copy4<<<(int)(HC / 4 + 255) / 256, 256>>>(Fv, rFv, (int)(HC / 4));

    const dim3 gC(Cq / BN,  Mq / BM);   // (8, 64)   N=1024
    const dim3 gH(HIDq / BN, Mq / BM);  // (32, 64)  N=4096

    // att branch
    ln_mix<3><<<Mq, 256>>>(x, ln1_g, ln1_b, tmk, tmv, tmr, xk, xv, xr);
    gemm_tf32<0><<<gC, 256, GEMM_SMEM>>>(xk, rWk, k,  nullptr, nullptr, Cq, Cq);
    gemm_tf32<0><<<gC, 256, GEMM_SMEM>>>(xv, rWv, v,  nullptr, nullptr, Cq, Cq);
    gemm_tf32<1><<<gC, 256, GEMM_SMEM>>>(xr, rWr, sr, nullptr, nullptr, Cq, Cq);

    wkv_phase_a<<<(NCH * Bq * Cq) / 256, 256>>>(k, v, td, Ca, Cb);
    wkv_scan   <<<(Bq * Cq) / 256, 256>>>(td, Ca, Cb, Sa, Sb);
    wkv_phase_b<<<(NCH * Bq * Cq) / 256, 256>>>(k, v, sr, td, tf, Sa, Sb, rw);

    gemm_tf32<3><<<gC, 256, GEMM_SMEM>>>(rw, rWo, x1, x, nullptr, Cq, Cq);

    // ffn branch
    ln_mix<2><<<Mq, 256>>>(x1, ln2_g, ln2_b, fmk, fmr, nullptr, fk, fr, nullptr);
    gemm_tf32<2><<<gH, 256, GEMM_SMEM>>>(fk, rFk, kk, nullptr, nullptr, HIDq, Cq);
    gemm_tf32<1><<<gC, 256, GEMM_SMEM>>>(fr, rFr, sg, nullptr, nullptr, Cq, Cq);
    gemm_tf32<4><<<gC, 256, GEMM_SMEM>>>(kk, rFv, out, x1, sg, Cq, HIDq);
}

// round 5
// speedup vs baseline: 1.0667x; 1.0667x over previous
#include <cuda_runtime.h>
#include <cstdint>

// Problem dims (fixed)
#define Bq   8
#define Tq   2048
#define Cq   1024
#define HIDq 4096
#define Mq   (Bq*Tq)        // 16384 rows
#define NCH  32             // WKV chunks
#define LCH  (Tq/NCH)       // 64 steps per chunk

// GEMM tiling: CTA tile 128x128 (128 threads), warp tile 64x64, BK=32 (128B rows)
#define BM     128
#define BN     128
#define BKK    32
#define STAGES 3
#define ASTGB  (BM*BKK*4)            // 16384 bytes per A stage
#define BSTGB  (BN*BKK*4)            // 16384 bytes per B stage
#define STGB   (ASTGB + BSTGB)       // 32768 bytes per stage
#define GEMM_SMEM (STAGES*STGB + 1024)   // 99328

// ---------------- scratch (static device globals; no allocation) ----------
__device__ float g_xk[(size_t)Mq*Cq];
__device__ float g_xv[(size_t)Mq*Cq];
__device__ float g_xr[(size_t)Mq*Cq];
__device__ float g_k [(size_t)Mq*Cq];
__device__ float g_v [(size_t)Mq*Cq];
__device__ float g_sr[(size_t)Mq*Cq];
__device__ float g_rw[(size_t)Mq*Cq];
__device__ float g_x1[(size_t)Mq*Cq];
__device__ float g_fk[(size_t)Mq*Cq];
__device__ float g_fr[(size_t)Mq*Cq];
__device__ float g_sg[(size_t)Mq*Cq];
__device__ float g_kk[(size_t)Mq*HIDq];
__device__ float g_Ca[(size_t)NCH*Bq*Cq];
__device__ float g_Cb[(size_t)NCH*Bq*Cq];
__device__ float g_Sa[(size_t)NCH*Bq*Cq];
__device__ float g_Sb[(size_t)NCH*Bq*Cq];
// rounded weight copies: Wk,Wv,Wr,Wo,Fr (C*C each) then Fk,Fv (HID*C each)
__device__ float g_wt[(size_t)5*Cq*Cq + (size_t)2*HIDq*Cq];

// ---------------- helpers --------------------------------------------------
__device__ __forceinline__ uint32_t f2tf(float x) {
    uint32_t r;
    asm("cvt.rna.tf32.f32 %0, %1;" : "=r"(r) : "f"(x));
    return r;
}
__device__ __forceinline__ float rtf(float x) { return __uint_as_float(f2tf(x)); }

__device__ __forceinline__ void mma_tf32(float* c, const uint32_t* a, const uint32_t* b) {
    asm volatile(
        "mma.sync.aligned.m16n8k8.row.col.f32.tf32.tf32.f32 "
        "{%0,%1,%2,%3}, {%4,%5,%6,%7}, {%8,%9}, {%0,%1,%2,%3};"
        : "+f"(c[0]), "+f"(c[1]), "+f"(c[2]), "+f"(c[3])
        : "r"(a[0]), "r"(a[1]), "r"(a[2]), "r"(a[3]), "r"(b[0]), "r"(b[1]));
}

__device__ __forceinline__ uint32_t smem_u32(const void* p) {
    uint32_t a;
    asm("{ .reg .u64 t; cvta.to.shared.u64 t, %1; cvt.u32.u64 %0, t; }" : "=r"(a) : "l"(p));
    return a;
}
__device__ __forceinline__ void cp16(uint32_t dst, const float* src) {
    asm volatile("cp.async.cg.shared.global [%0], [%1], 16;" :: "r"(dst), "l"(src));
}
__device__ __forceinline__ void cp_commit() { asm volatile("cp.async.commit_group;"); }
template<int N> __device__ __forceinline__ void cp_wait() {
    asm volatile("cp.async.wait_group %0;" :: "n"(N));
}

// block-wide reduce of 4 values (256 threads)
__device__ __forceinline__ void bred4(float& a, float& b, float& c, float& d) {
    #pragma unroll
    for (int o = 16; o; o >>= 1) {
        a += __shfl_xor_sync(0xffffffffu, a, o);
        b += __shfl_xor_sync(0xffffffffu, b, o);
        c += __shfl_xor_sync(0xffffffffu, c, o);
        d += __shfl_xor_sync(0xffffffffu, d, o);
    }
    __shared__ float sm[8][4];
    int w = threadIdx.x >> 5, l = threadIdx.x & 31;
    if (l == 0) { sm[w][0] = a; sm[w][1] = b; sm[w][2] = c; sm[w][3] = d; }
    __syncthreads();
    a = b = c = d = 0.f;
    #pragma unroll
    for (int j = 0; j < 8; j++) { a += sm[j][0]; b += sm[j][1]; c += sm[j][2]; d += sm[j][3]; }
}

// ---------------- weight rounding (RNE to tf32, stored as fp32) ------------
__global__ __launch_bounds__(256) void round_copy4(const float* __restrict__ src,
                                                   float* __restrict__ dst, int n4)
{
    const int i = blockIdx.x * blockDim.x + threadIdx.x;
    if (i >= n4) return;
    float4 v = reinterpret_cast<const float4*>(src)[i];
    v.x = rtf(v.x); v.y = rtf(v.y); v.z = rtf(v.z); v.w = rtf(v.w);
    reinterpret_cast<float4*>(dst)[i] = v;
}

// ---------------- fused LayerNorm + time-shift + token-mix -----------------
template<int NOUT>
__global__ __launch_bounds__(256) void ln_mix(
    const float* __restrict__ x, const float* __restrict__ g, const float* __restrict__ be,
    const float* __restrict__ m0, const float* __restrict__ m1, const float* __restrict__ m2,
    float* __restrict__ o0, float* __restrict__ o1, float* __restrict__ o2)
{
    const int row = blockIdx.x;          // b*T + t
    const int t   = row & (Tq - 1);
    const int i   = threadIdx.x;         // one float4 per thread (C/4 = 256)

    const float4 v = reinterpret_cast<const float4*>(x + (size_t)row * Cq)[i];
    float4 u = make_float4(0.f, 0.f, 0.f, 0.f);
    if (t > 0) u = reinterpret_cast<const float4*>(x + (size_t)(row - 1) * Cq)[i];

    float s  = v.x + v.y + v.z + v.w;
    float ss = v.x*v.x + v.y*v.y + v.z*v.z + v.w*v.w;
    float sp = u.x + u.y + u.z + u.w;
    float sq = u.x*u.x + u.y*u.y + u.z*u.z + u.w*u.w;
    bred4(s, ss, sp, sq);

    const float inv = 1.f / (float)Cq;
    const float mC = s * inv;
    const float rs = rsqrtf(ss * inv - mC * mC + 1e-5f);
    const float mP = sp * inv;
    const float rp = rsqrtf(sq * inv - mP * mP + 1e-5f);

    const float4 g4 = reinterpret_cast<const float4*>(g)[i];
    const float4 b4 = reinterpret_cast<const float4*>(be)[i];

    float xa[4], xx[4];
    const float* vv = &v.x; const float* uu = &u.x;
    const float* gg = &g4.x; const float* bb = &b4.x;
    #pragma unroll
    for (int j = 0; j < 4; j++) {
        xa[j] = (vv[j] - mC) * rs * gg[j] + bb[j];
        xx[j] = (t > 0) ? ((uu[j] - mP) * rp * gg[j] + bb[j]) : 0.f;
    }

    const size_t oi = (size_t)row * (Cq / 4) + i;
    {
        const float4 w4 = reinterpret_cast<const float4*>(m0)[i];
        const float* ww = &w4.x; float4 r; float* rr = &r.x;
        #pragma unroll
        for (int j = 0; j < 4; j++) rr[j] = rtf(xa[j] * ww[j] + xx[j] * (1.f - ww[j]));
        reinterpret_cast<float4*>(o0)[oi] = r;
    }
    {
        const float4 w4 = reinterpret_cast<const float4*>(m1)[i];
        const float* ww = &w4.x; float4 r; float* rr = &r.x;
        #pragma unroll
        for (int j = 0; j < 4; j++) rr[j] = rtf(xa[j] * ww[j] + xx[j] * (1.f - ww[j]));
        reinterpret_cast<float4*>(o1)[oi] = r;
    }
    if (NOUT == 3) {
        const float4 w4 = reinterpret_cast<const float4*>(m2)[i];
        const float* ww = &w4.x; float4 r; float* rr = &r.x;
        #pragma unroll
        for (int j = 0; j < 4; j++) rr[j] = rtf(xa[j] * ww[j] + xx[j] * (1.f - ww[j]));
        reinterpret_cast<float4*>(o2)[oi] = r;
    }
}

// ---------------- tf32 GEMM, 128x128 tile, 4 warps @ 64x64, 3-stage cp.async
// out[m,n] = sum_k A[m,k]*W[n,k]. A,W pre-rounded to tf32 values.
// Smem: XOR-swizzled 128B rows (conflict-free, no padding). 2 CTAs/SM.
// EPI: 0 none | 1 sigmoid | 2 relu^2 (tf32-rounded) | 3 aux1+acc | 4 aux1+aux2*acc

__device__ __forceinline__ void fill_tile(uint32_t sbase, int stage,
    const float* __restrict__ Ag, const float* __restrict__ Wg, int K, int k0, int tid)
{
    const uint32_t sa = sbase + (uint32_t)stage * STGB;
    #pragma unroll
    for (int p = 0; p < 8; p++) {            // A: 128 rows x 8 chunks = 1024
        const int id  = tid + p * 128;
        const int row = id >> 3, c = id & 7;
        const uint32_t off = (uint32_t)(row * 128 + c * 16);
        cp16(sa + (off ^ ((off >> 3) & 0x70)), Ag + (size_t)row * K + k0 + c * 4);
    }
    const uint32_t sb = sa + ASTGB;
    #pragma unroll
    for (int p = 0; p < 8; p++) {            // B: 128 rows x 8 chunks = 1024
        const int id  = tid + p * 128;
        const int row = id >> 3, c = id & 7;
        const uint32_t off = (uint32_t)(row * 128 + c * 16);
        cp16(sb + (off ^ ((off >> 3) & 0x70)), Wg + (size_t)row * K + k0 + c * 4);
    }
}

// swizzled float index within a tile: row*32 floats, col in floats
__device__ __forceinline__ int swidx(int row, int col) {
    return row * 32 + (col ^ ((row & 7) * 4));
}

template<int EPI>
__device__ __forceinline__ void epi_store(float* __restrict__ out, size_t idx,
    float c0, float c1, const float* __restrict__ a1, const float* __restrict__ a2)
{
    if (EPI == 1) { c0 = 1.f / (1.f + __expf(-c0)); c1 = 1.f / (1.f + __expf(-c1)); }
    else if (EPI == 2) {
        c0 = fmaxf(c0, 0.f); c0 = rtf(c0 * c0);
        c1 = fmaxf(c1, 0.f); c1 = rtf(c1 * c1);
    }
    else if (EPI == 3) { c0 += a1[idx]; c1 += a1[idx + 1]; }
    else if (EPI == 4) { c0 = a1[idx] + a2[idx] * c0; c1 = a1[idx + 1] + a2[idx + 1] * c1; }
    float2 t; t.x = c0; t.y = c1;
    *reinterpret_cast<float2*>(out + idx) = t;
}

template<int EPI>
__global__ __launch_bounds__(128, 2) void gemm_tf32(
    const float* __restrict__ A, const float* __restrict__ W, float* __restrict__ out,
    const float* __restrict__ aux1, const float* __restrict__ aux2, int N, int K)
{
    extern __shared__ float dsm[];
    const uint32_t sbase = (smem_u32(dsm) + 1023u) & ~1023u;
    float* smf = (float*)((char*)dsm + (sbase - smem_u32(dsm)));

    const int tid  = threadIdx.x;
    const int lane = tid & 31;
    const int warp = tid >> 5;
    const int wm   = warp >> 1;   // 0..1 -> 64 rows each
    const int wn   = warp & 1;    // 0..1 -> 64 cols each

    const int brow = blockIdx.y * BM;
    const int bcol = blockIdx.x * BN;
    const float* Ag = A + (size_t)brow * K;
    const float* Wg = W + (size_t)bcol * K;
    const int ntiles = K / BKK;

    // prologue
    fill_tile(sbase, 0, Ag, Wg, K, 0,   tid); cp_commit();
    fill_tile(sbase, 1, Ag, Wg, K, BKK, tid); cp_commit();

    float acc[4][8][4];
    #pragma unroll
    for (int mt = 0; mt < 4; mt++)
        #pragma unroll
        for (int nt = 0; nt < 8; nt++)
            #pragma unroll
            for (int q = 0; q < 4; q++) acc[mt][nt][q] = 0.f;

    const int qrow = lane >> 2;     // 0..7
    const int qcol = lane & 3;      // 0..3

    for (int t = 0; t < ntiles; t++) {
        cp_wait<STAGES - 2>();
        __syncthreads();

        const int tp = t + STAGES - 1;
        if (tp < ntiles) fill_tile(sbase, tp % STAGES, Ag, Wg, K, tp * BKK, tid);
        cp_commit();

        const uint32_t* a_s = reinterpret_cast<const uint32_t*>(smf + (size_t)(t % STAGES) * (STGB / 4));
        const uint32_t* b_s = a_s + (ASTGB / 4);

        #pragma unroll
        for (int ks = 0; ks < 4; ks++) {
            const int k8 = ks * 8;
            uint32_t a[4][4], b[8][2];
            #pragma unroll
            for (int mt = 0; mt < 4; mt++) {
                const int r0 = wm * 64 + mt * 16 + qrow;
                a[mt][0] = a_s[swidx(r0,     k8 + qcol)];
                a[mt][1] = a_s[swidx(r0 + 8, k8 + qcol)];
                a[mt][2] = a_s[swidx(r0,     k8 + 4 + qcol)];
                a[mt][3] = a_s[swidx(r0 + 8, k8 + 4 + qcol)];
            }
            #pragma unroll
            for (int nt = 0; nt < 8; nt++) {
                const int c0 = wn * 64 + nt * 8 + qrow;
                b[nt][0] = b_s[swidx(c0, k8 + qcol)];
                b[nt][1] = b_s[swidx(c0, k8 + 4 + qcol)];
            }
            #pragma unroll
            for (int mt = 0; mt < 4; mt++)
                #pragma unroll
                for (int nt = 0; nt < 8; nt++)
                    mma_tf32(acc[mt][nt], a[mt], b[nt]);
        }
        __syncthreads();
    }

    // epilogue straight from registers
    #pragma unroll
    for (int mt = 0; mt < 4; mt++) {
        #pragma unroll
        for (int nt = 0; nt < 8; nt++) {
            const int row = brow + wm * 64 + mt * 16 + qrow;
            const int col = bcol + wn * 64 + nt * 8 + qcol * 2;
            const size_t i0 = (size_t)row * N + col;
            const size_t i1 = (size_t)(row + 8) * N + col;
            epi_store<EPI>(out, i0, acc[mt][nt][0], acc[mt][nt][1], aux1, aux2);
            epi_store<EPI>(out, i1, acc[mt][nt][2], acc[mt][nt][3], aux1, aux2);
        }
    }
}

// ---------------- WKV chunked scan ------------------------------------------
__global__ __launch_bounds__(256) void wkv_phase_a(
    const float* __restrict__ k, const float* __restrict__ v,
    const float* __restrict__ td, float* __restrict__ Ca, float* __restrict__ Cb)
{
    const int gid = blockIdx.x * blockDim.x + threadIdx.x;   // < NCH*B*C
    const int c  = gid & (Cq - 1);
    const int r  = gid >> 10;
    const int b  = r & (Bq - 1);
    const int ch = r >> 3;
    const float w  = -expf(td[c]);
    const float dw = expf(w);
    const size_t base = ((size_t)(b * Tq + ch * LCH)) * Cq + c;
    float sa = 0.f, sb = 0.f;
    #pragma unroll 4
    for (int i = 0; i < LCH; i++) {
        const float kt = k[base + (size_t)i * Cq];
        const float vt = v[base + (size_t)i * Cq];
        const float ek = __expf(kt);
        sa = fmaf(dw, sa, ek * vt);
        sb = fmaf(dw, sb, ek);
    }
    Ca[gid] = sa; Cb[gid] = sb;
}

__global__ __launch_bounds__(256) void wkv_scan(
    const float* __restrict__ td,
    const float* __restrict__ Ca, const float* __restrict__ Cb,
    float* __restrict__ Sa, float* __restrict__ Sb)
{
    const int sid = blockIdx.x * blockDim.x + threadIdx.x;   // < B*C
    const int c = sid & (Cq - 1);
    const float w  = -expf(td[c]);
    const float dL = expf((float)LCH * w);
    float sa = 0.f, sb = 0.f;
    #pragma unroll
    for (int ch = 0; ch < NCH; ch++) {
        const int idx = ch * (Bq * Cq) + sid;
        Sa[idx] = sa; Sb[idx] = sb;
        sa = fmaf(dL, sa, Ca[idx]);
        sb = fmaf(dL, sb, Cb[idx]);
    }
}

__global__ __launch_bounds__(256) void wkv_phase_b(
    const float* __restrict__ k, const float* __restrict__ v, const float* __restrict__ sr,
    const float* __restrict__ td, const float* __restrict__ tf,
    const float* __restrict__ Sa, const float* __restrict__ Sb, float* __restrict__ out)
{
    const int gid = blockIdx.x * blockDim.x + threadIdx.x;
    const int c  = gid & (Cq - 1);
    const int r  = gid >> 10;
    const int b  = r & (Bq - 1);
    const int ch = r >> 3;
    const float w  = -expf(td[c]);
    const float dw = expf(w);
    const float eu = expf(tf[c]);
    float a = Sa[gid], bb = Sb[gid];
    const size_t base = ((size_t)(b * Tq + ch * LCH)) * Cq + c;
    #pragma unroll 4
    for (int i = 0; i < LCH; i++) {
        const size_t off = base + (size_t)i * Cq;
        const float kt = k[off];
        const float vt = v[off];
        const float ek = __expf(kt);
        const float euk = eu * ek;
        const float y = (a + euk * vt) / (bb + euk);
        out[off] = rtf(sr[off] * y);          // feeds Wo GEMM only
        a  = fmaf(dw, a,  ek * vt);
        bb = fmaf(dw, bb, ek);
    }
}

// ---------------- launch -----------------------------------------------------
extern "C" void kernel_launch(void* const* d_in, const int* in_sizes, int n_in,
                              void* d_out, int out_size)
{
    const float* x     = (const float*)d_in[0];
    const float* ln1_g = (const float*)d_in[1];
    const float* ln1_b = (const float*)d_in[2];
    const float* ln2_g = (const float*)d_in[3];
    const float* ln2_b = (const float*)d_in[4];
    const float* td    = (const float*)d_in[5];
    const float* tf    = (const float*)d_in[6];
    const float* tmk   = (const float*)d_in[7];
    const float* tmv   = (const float*)d_in[8];
    const float* tmr   = (const float*)d_in[9];
    const float* Wk    = (const float*)d_in[10];
    const float* Wv    = (const float*)d_in[11];
    const float* Wr    = (const float*)d_in[12];
    const float* Wo    = (const float*)d_in[13];
    const float* fmk   = (const float*)d_in[14];
    const float* fmr   = (const float*)d_in[15];
    const float* Fk    = (const float*)d_in[16];
    const float* Fr    = (const float*)d_in[17];
    const float* Fv    = (const float*)d_in[18];
    float* out = (float*)d_out;

    float *xk, *xv, *xr, *k, *v, *sr, *rw, *x1, *fk, *fr, *sg, *kk, *Ca, *Cb, *Sa, *Sb, *wt;
    cudaGetSymbolAddress((void**)&xk, g_xk);
    cudaGetSymbolAddress((void**)&xv, g_xv);
    cudaGetSymbolAddress((void**)&xr, g_xr);
    cudaGetSymbolAddress((void**)&k,  g_k);
    cudaGetSymbolAddress((void**)&v,  g_v);
    cudaGetSymbolAddress((void**)&sr, g_sr);
    cudaGetSymbolAddress((void**)&rw, g_rw);
    cudaGetSymbolAddress((void**)&x1, g_x1);
    cudaGetSymbolAddress((void**)&fk, g_fk);
    cudaGetSymbolAddress((void**)&fr, g_fr);
    cudaGetSymbolAddress((void**)&sg, g_sg);
    cudaGetSymbolAddress((void**)&kk, g_kk);
    cudaGetSymbolAddress((void**)&Ca, g_Ca);
    cudaGetSymbolAddress((void**)&Cb, g_Cb);
    cudaGetSymbolAddress((void**)&Sa, g_Sa);
    cudaGetSymbolAddress((void**)&Sb, g_Sb);
    cudaGetSymbolAddress((void**)&wt, g_wt);

    const size_t CC = (size_t)Cq * Cq;          // 1M
    const size_t HC = (size_t)HIDq * Cq;        // 4M
    float* rWk = wt;
    float* rWv = wt + CC;
    float* rWr = wt + 2 * CC;
    float* rWo = wt + 3 * CC;
    float* rFr = wt + 4 * CC;
    float* rFk = wt + 5 * CC;
    float* rFv = wt + 5 * CC + HC;

    cudaFuncSetAttribute(gemm_tf32<0>, cudaFuncAttributeMaxDynamicSharedMemorySize, GEMM_SMEM);
    cudaFuncSetAttribute(gemm_tf32<1>, cudaFuncAttributeMaxDynamicSharedMemorySize, GEMM_SMEM);
    cudaFuncSetAttribute(gemm_tf32<2>, cudaFuncAttributeMaxDynamicSharedMemorySize, GEMM_SMEM);
    cudaFuncSetAttribute(gemm_tf32<3>, cudaFuncAttributeMaxDynamicSharedMemorySize, GEMM_SMEM);
    cudaFuncSetAttribute(gemm_tf32<4>, cudaFuncAttributeMaxDynamicSharedMemorySize, GEMM_SMEM);

    // round weights (RNE->tf32) into scratch
    round_copy4<<<(int)(CC / 4 + 255) / 256, 256>>>(Wk, rWk, (int)(CC / 4));
    round_copy4<<<(int)(CC / 4 + 255) / 256, 256>>>(Wv, rWv, (int)(CC / 4));
    round_copy4<<<(int)(CC / 4 + 255) / 256, 256>>>(Wr, rWr, (int)(CC / 4));
    round_copy4<<<(int)(CC / 4 + 255) / 256, 256>>>(Wo, rWo, (int)(CC / 4));
    round_copy4<<<(int)(CC / 4 + 255) / 256, 256>>>(Fr, rFr, (int)(CC / 4));
    round_copy4<<<(int)(HC / 4 + 255) / 256, 256>>>(Fk, rFk, (int)(HC / 4));
    round_copy4<<<(int)(HC / 4 + 255) / 256, 256>>>(Fv, rFv, (int)(HC / 4));

    const dim3 gC(Cq / BN,  Mq / BM);   // (8, 128)   N=1024
    const dim3 gH(HIDq / BN, Mq / BM);  // (32, 128)  N=4096

    // att branch
    ln_mix<3><<<Mq, 256>>>(x, ln1_g, ln1_b, tmk, tmv, tmr, xk, xv, xr);
    gemm_tf32<0><<<gC, 128, GEMM_SMEM>>>(xk, rWk, k,  nullptr, nullptr, Cq, Cq);
    gemm_tf32<0><<<gC, 128, GEMM_SMEM>>>(xv, rWv, v,  nullptr, nullptr, Cq, Cq);
    gemm_tf32<1><<<gC, 128, GEMM_SMEM>>>(xr, rWr, sr, nullptr, nullptr, Cq, Cq);

    wkv_phase_a<<<(NCH * Bq * Cq) / 256, 256>>>(k, v, td, Ca, Cb);
    wkv_scan   <<<(Bq * Cq) / 256, 256>>>(td, Ca, Cb, Sa, Sb);
    wkv_phase_b<<<(NCH * Bq * Cq) / 256, 256>>>(k, v, sr, td, tf, Sa, Sb, rw);

    gemm_tf32<3><<<gC, 128, GEMM_SMEM>>>(rw, rWo, x1, x, nullptr, Cq, Cq);

    // ffn branch
    ln_mix<2><<<Mq, 256>>>(x1, ln2_g, ln2_b, fmk, fmr, nullptr, fk, fr, nullptr);
    gemm_tf32<2><<<gH, 128, GEMM_SMEM>>>(fk, rFk, kk, nullptr, nullptr, HIDq, Cq);
    gemm_tf32<1><<<gC, 128, GEMM_SMEM>>>(fr, rFr, sg, nullptr, nullptr, Cq, Cq);
    gemm_tf32<4><<<gC, 128, GEMM_SMEM>>>(kk, rFv, out, x1, sg, Cq, HIDq);
}

// round 6
// speedup vs baseline: 1.8975x; 1.7788x over previous
#include <cuda_runtime.h>
#include <cuda_fp16.h>
#include <cstdint>

// Problem dims (fixed)
#define Bq   8
#define Tq   2048
#define Cq   1024
#define HIDq 4096
#define Mq   (Bq*Tq)        // 16384 rows
#define NCH  32             // WKV chunks
#define LCH  (Tq/NCH)       // 64 steps per chunk

// GEMM tiling: CTA 128x128 (128 thr), warp 64x64, BK=64 fp16 (128B rows)
#define BM     128
#define BN     128
#define BKK    64
#define STAGES 3
#define ASTGB  (BM*128)              // 16384 bytes per A stage
#define BSTGB  (BN*128)              // 16384 bytes per B stage
#define STGB   (ASTGB + BSTGB)       // 32768 per stage
#define GEMM_SMEM (STAGES*STGB + 1024)   // 99328 -> 2 CTAs/SM

// ---------------- scratch (static device globals; no allocation) ----------
__device__ __half g_xk[(size_t)Mq*Cq];
__device__ __half g_xv[(size_t)Mq*Cq];
__device__ __half g_xr[(size_t)Mq*Cq];
__device__ __half g_fk[(size_t)Mq*Cq];
__device__ __half g_fr[(size_t)Mq*Cq];
__device__ __half g_rw[(size_t)Mq*Cq];
__device__ __half g_kk[(size_t)Mq*HIDq];
__device__ float  g_k [(size_t)Mq*Cq];
__device__ float  g_v [(size_t)Mq*Cq];
__device__ float  g_sr[(size_t)Mq*Cq];
__device__ float  g_x1[(size_t)Mq*Cq];
__device__ float  g_sg[(size_t)Mq*Cq];
__device__ float  g_Ca[(size_t)NCH*Bq*Cq];
__device__ float  g_Cb[(size_t)NCH*Bq*Cq];
__device__ float  g_Sa[(size_t)NCH*Bq*Cq];
__device__ float  g_Sb[(size_t)NCH*Bq*Cq];
// half weights: Wk,Wv,Wr,Wo,Fr (C*C each) then Fk,Fv (HID*C each)
__device__ __half g_wh[(size_t)5*Cq*Cq + (size_t)2*HIDq*Cq];

// ---------------- helpers --------------------------------------------------
__device__ __forceinline__ void mma_f16(float* c, const uint32_t* a, const uint32_t* b) {
    asm volatile(
        "mma.sync.aligned.m16n8k16.row.col.f32.f16.f16.f32 "
        "{%0,%1,%2,%3}, {%4,%5,%6,%7}, {%8,%9}, {%0,%1,%2,%3};"
        : "+f"(c[0]), "+f"(c[1]), "+f"(c[2]), "+f"(c[3])
        : "r"(a[0]), "r"(a[1]), "r"(a[2]), "r"(a[3]), "r"(b[0]), "r"(b[1]));
}

__device__ __forceinline__ uint32_t smem_u32(const void* p) {
    uint32_t a;
    asm("{ .reg .u64 t; cvta.to.shared.u64 t, %1; cvt.u32.u64 %0, t; }" : "=r"(a) : "l"(p));
    return a;
}
__device__ __forceinline__ void cp16(uint32_t dst, const void* src) {
    asm volatile("cp.async.cg.shared.global [%0], [%1], 16;" :: "r"(dst), "l"(src));
}
__device__ __forceinline__ void cp_commit() { asm volatile("cp.async.commit_group;"); }
template<int N> __device__ __forceinline__ void cp_wait() {
    asm volatile("cp.async.wait_group %0;" :: "n"(N));
}

// block-wide reduce of 4 values (256 threads)
__device__ __forceinline__ void bred4(float& a, float& b, float& c, float& d) {
    #pragma unroll
    for (int o = 16; o; o >>= 1) {
        a += __shfl_xor_sync(0xffffffffu, a, o);
        b += __shfl_xor_sync(0xffffffffu, b, o);
        c += __shfl_xor_sync(0xffffffffu, c, o);
        d += __shfl_xor_sync(0xffffffffu, d, o);
    }
    __shared__ float sm[8][4];
    int w = threadIdx.x >> 5, l = threadIdx.x & 31;
    if (l == 0) { sm[w][0] = a; sm[w][1] = b; sm[w][2] = c; sm[w][3] = d; }
    __syncthreads();
    a = b = c = d = 0.f;
    #pragma unroll
    for (int j = 0; j < 8; j++) { a += sm[j][0]; b += sm[j][1]; c += sm[j][2]; d += sm[j][3]; }
}

// ---------------- weight conversion fp32 -> fp16 ---------------------------
__global__ __launch_bounds__(256) void w2h5(
    const float* __restrict__ w0, const float* __restrict__ w1, const float* __restrict__ w2,
    const float* __restrict__ w3, const float* __restrict__ w4, __half* __restrict__ dst)
{
    const size_t CC = (size_t)Cq * Cq;
    const float* src = (blockIdx.y == 0) ? w0 : (blockIdx.y == 1) ? w1 :
                       (blockIdx.y == 2) ? w2 : (blockIdx.y == 3) ? w3 : w4;
    __half* d = dst + (size_t)blockIdx.y * CC;
    const int i = blockIdx.x * blockDim.x + threadIdx.x;   // < CC/4
    float4 v = reinterpret_cast<const float4*>(src)[i];
    __half2 h01 = __floats2half2_rn(v.x, v.y);
    __half2 h23 = __floats2half2_rn(v.z, v.w);
    uint2 u; u.x = *reinterpret_cast<uint32_t*>(&h01); u.y = *reinterpret_cast<uint32_t*>(&h23);
    reinterpret_cast<uint2*>(d)[i] = u;
}

__global__ __launch_bounds__(256) void w2h2(
    const float* __restrict__ w0, const float* __restrict__ w1, __half* __restrict__ dst)
{
    const size_t HC = (size_t)HIDq * Cq;
    const float* src = (blockIdx.y == 0) ? w0 : w1;
    __half* d = dst + (size_t)blockIdx.y * HC;
    const int i = blockIdx.x * blockDim.x + threadIdx.x;   // < HC/4
    float4 v = reinterpret_cast<const float4*>(src)[i];
    __half2 h01 = __floats2half2_rn(v.x, v.y);
    __half2 h23 = __floats2half2_rn(v.z, v.w);
    uint2 u; u.x = *reinterpret_cast<uint32_t*>(&h01); u.y = *reinterpret_cast<uint32_t*>(&h23);
    reinterpret_cast<uint2*>(d)[i] = u;
}

// ---------------- fused LayerNorm + time-shift + token-mix (half out) ------
template<int NOUT>
__global__ __launch_bounds__(256) void ln_mix(
    const float* __restrict__ x, const float* __restrict__ g, const float* __restrict__ be,
    const float* __restrict__ m0, const float* __restrict__ m1, const float* __restrict__ m2,
    __half* __restrict__ o0, __half* __restrict__ o1, __half* __restrict__ o2)
{
    const int row = blockIdx.x;          // b*T + t
    const int t   = row & (Tq - 1);
    const int i   = threadIdx.x;         // one float4 per thread (C/4 = 256)

    const float4 v = reinterpret_cast<const float4*>(x + (size_t)row * Cq)[i];
    float4 u = make_float4(0.f, 0.f, 0.f, 0.f);
    if (t > 0) u = reinterpret_cast<const float4*>(x + (size_t)(row - 1) * Cq)[i];

    float s  = v.x + v.y + v.z + v.w;
    float ss = v.x*v.x + v.y*v.y + v.z*v.z + v.w*v.w;
    float sp = u.x + u.y + u.z + u.w;
    float sq = u.x*u.x + u.y*u.y + u.z*u.z + u.w*u.w;
    bred4(s, ss, sp, sq);

    const float inv = 1.f / (float)Cq;
    const float mC = s * inv;
    const float rs = rsqrtf(ss * inv - mC * mC + 1e-5f);
    const float mP = sp * inv;
    const float rp = rsqrtf(sq * inv - mP * mP + 1e-5f);

    const float4 g4 = reinterpret_cast<const float4*>(g)[i];
    const float4 b4 = reinterpret_cast<const float4*>(be)[i];

    float xa[4], xx[4];
    const float* vv = &v.x; const float* uu = &u.x;
    const float* gg = &g4.x; const float* bb = &b4.x;
    #pragma unroll
    for (int j = 0; j < 4; j++) {
        xa[j] = (vv[j] - mC) * rs * gg[j] + bb[j];
        xx[j] = (t > 0) ? ((uu[j] - mP) * rp * gg[j] + bb[j]) : 0.f;
    }

    const size_t oi = (size_t)row * (Cq / 4) + i;
    {
        const float4 w4 = reinterpret_cast<const float4*>(m0)[i];
        const float* ww = &w4.x; float r[4];
        #pragma unroll
        for (int j = 0; j < 4; j++) r[j] = xa[j] * ww[j] + xx[j] * (1.f - ww[j]);
        __half2 h01 = __floats2half2_rn(r[0], r[1]);
        __half2 h23 = __floats2half2_rn(r[2], r[3]);
        uint2 o; o.x = *reinterpret_cast<uint32_t*>(&h01); o.y = *reinterpret_cast<uint32_t*>(&h23);
        reinterpret_cast<uint2*>(o0)[oi] = o;
    }
    {
        const float4 w4 = reinterpret_cast<const float4*>(m1)[i];
        const float* ww = &w4.x; float r[4];
        #pragma unroll
        for (int j = 0; j < 4; j++) r[j] = xa[j] * ww[j] + xx[j] * (1.f - ww[j]);
        __half2 h01 = __floats2half2_rn(r[0], r[1]);
        __half2 h23 = __floats2half2_rn(r[2], r[3]);
        uint2 o; o.x = *reinterpret_cast<uint32_t*>(&h01); o.y = *reinterpret_cast<uint32_t*>(&h23);
        reinterpret_cast<uint2*>(o1)[oi] = o;
    }
    if (NOUT == 3) {
        const float4 w4 = reinterpret_cast<const float4*>(m2)[i];
        const float* ww = &w4.x; float r[4];
        #pragma unroll
        for (int j = 0; j < 4; j++) r[j] = xa[j] * ww[j] + xx[j] * (1.f - ww[j]);
        __half2 h01 = __floats2half2_rn(r[0], r[1]);
        __half2 h23 = __floats2half2_rn(r[2], r[3]);
        uint2 o; o.x = *reinterpret_cast<uint32_t*>(&h01); o.y = *reinterpret_cast<uint32_t*>(&h23);
        reinterpret_cast<uint2*>(o2)[oi] = o;
    }
}

// ---------------- fp16 GEMM, 128x128 tile, 4 warps @ 64x64, 3-stage cp.async
// out[m,n] = sum_k A[m,k]*W[n,k], A/W half, accumulate fp32 in MMA.
// Smem: XOR-swizzled 128B rows. 2 CTAs/SM.
// EPI: 0 none(f32) | 1 sigmoid(f32) | 2 relu^2 -> HALF out | 3 aux1+acc | 4 aux1+aux2*acc

__device__ __forceinline__ void fill_tile(uint32_t sbase, int stage,
    const __half* __restrict__ Ag, const __half* __restrict__ Wg, int K, int k0, int tid)
{
    const uint32_t sa = sbase + (uint32_t)stage * STGB;
    #pragma unroll
    for (int p = 0; p < 8; p++) {            // A: 128 rows x 8 chunks = 1024
        const int id  = tid + p * 128;
        const int row = id >> 3, c = id & 7;
        const uint32_t off = (uint32_t)(row * 128 + c * 16);
        cp16(sa + (off ^ ((off >> 3) & 0x70)), Ag + (size_t)row * K + k0 + c * 8);
    }
    const uint32_t sb = sa + ASTGB;
    #pragma unroll
    for (int p = 0; p < 8; p++) {            // B: 128 rows x 8 chunks = 1024
        const int id  = tid + p * 128;
        const int row = id >> 3, c = id & 7;
        const uint32_t off = (uint32_t)(row * 128 + c * 16);
        cp16(sb + (off ^ ((off >> 3) & 0x70)), Wg + (size_t)row * K + k0 + c * 8);
    }
}

// swizzled uint32 index within a tile: 32 uint32 (=64 fp16) per row
__device__ __forceinline__ int swidx(int row, int cu) {
    return row * 32 + (cu ^ ((row & 7) * 4));
}

template<int EPI>
__device__ __forceinline__ void epi_store(void* __restrict__ out, size_t idx,
    float c0, float c1, const float* __restrict__ a1, const float* __restrict__ a2)
{
    if (EPI == 2) {
        c0 = fmaxf(c0, 0.f); c0 *= c0;
        c1 = fmaxf(c1, 0.f); c1 *= c1;
        __half2 h = __floats2half2_rn(c0, c1);
        *reinterpret_cast<__half2*>((__half*)out + idx) = h;
        return;
    }
    if (EPI == 1) { c0 = 1.f / (1.f + __expf(-c0)); c1 = 1.f / (1.f + __expf(-c1)); }
    else if (EPI == 3) { c0 += a1[idx]; c1 += a1[idx + 1]; }
    else if (EPI == 4) { c0 = a1[idx] + a2[idx] * c0; c1 = a1[idx + 1] + a2[idx + 1] * c1; }
    float2 t; t.x = c0; t.y = c1;
    *reinterpret_cast<float2*>((float*)out + idx) = t;
}

template<int EPI>
__global__ __launch_bounds__(128, 2) void gemm_f16(
    const __half* __restrict__ A, const __half* __restrict__ W, void* __restrict__ out,
    const float* __restrict__ aux1, const float* __restrict__ aux2, int N, int K)
{
    extern __shared__ float dsm[];
    const uint32_t sbase = (smem_u32(dsm) + 1023u) & ~1023u;
    float* smf = (float*)((char*)dsm + (sbase - smem_u32(dsm)));

    const int tid  = threadIdx.x;
    const int lane = tid & 31;
    const int warp = tid >> 5;
    const int wm   = warp >> 1;   // 0..1 -> 64 rows each
    const int wn   = warp & 1;    // 0..1 -> 64 cols each

    const int brow = blockIdx.y * BM;
    const int bcol = blockIdx.x * BN;
    const __half* Ag = A + (size_t)brow * K;
    const __half* Wg = W + (size_t)bcol * K;
    const int ntiles = K / BKK;

    // prologue
    fill_tile(sbase, 0, Ag, Wg, K, 0,   tid); cp_commit();
    fill_tile(sbase, 1, Ag, Wg, K, BKK, tid); cp_commit();

    float acc[4][8][4];
    #pragma unroll
    for (int mt = 0; mt < 4; mt++)
        #pragma unroll
        for (int nt = 0; nt < 8; nt++)
            #pragma unroll
            for (int q = 0; q < 4; q++) acc[mt][nt][q] = 0.f;

    const int qrow = lane >> 2;     // 0..7
    const int qcol = lane & 3;      // 0..3

    for (int t = 0; t < ntiles; t++) {
        cp_wait<STAGES - 2>();
        __syncthreads();

        const int tp = t + STAGES - 1;
        if (tp < ntiles) fill_tile(sbase, tp % STAGES, Ag, Wg, K, tp * BKK, tid);
        cp_commit();

        const uint32_t* a_s = reinterpret_cast<const uint32_t*>(smf + (size_t)(t % STAGES) * (STGB / 4));
        const uint32_t* b_s = a_s + (ASTGB / 4);

        #pragma unroll
        for (int ks = 0; ks < 4; ks++) {      // 4 x k16 = K64
            const int k8 = ks * 8;            // uint32 col base
            uint32_t a[4][4], b[8][2];
            #pragma unroll
            for (int mt = 0; mt < 4; mt++) {
                const int r0 = wm * 64 + mt * 16 + qrow;
                a[mt][0] = a_s[swidx(r0,     k8 + qcol)];
                a[mt][1] = a_s[swidx(r0 + 8, k8 + qcol)];
                a[mt][2] = a_s[swidx(r0,     k8 + 4 + qcol)];
                a[mt][3] = a_s[swidx(r0 + 8, k8 + 4 + qcol)];
            }
            #pragma unroll
            for (int nt = 0; nt < 8; nt++) {
                const int c0 = wn * 64 + nt * 8 + qrow;
                b[nt][0] = b_s[swidx(c0, k8 + qcol)];
                b[nt][1] = b_s[swidx(c0, k8 + 4 + qcol)];
            }
            #pragma unroll
            for (int mt = 0; mt < 4; mt++)
                #pragma unroll
                for (int nt = 0; nt < 8; nt++)
                    mma_f16(acc[mt][nt], a[mt], b[nt]);
        }
        __syncthreads();
    }

    // epilogue straight from registers
    #pragma unroll
    for (int mt = 0; mt < 4; mt++) {
        #pragma unroll
        for (int nt = 0; nt < 8; nt++) {
            const int row = brow + wm * 64 + mt * 16 + qrow;
            const int col = bcol + wn * 64 + nt * 8 + qcol * 2;
            const size_t i0 = (size_t)row * N + col;
            const size_t i1 = (size_t)(row + 8) * N + col;
            epi_store<EPI>(out, i0, acc[mt][nt][0], acc[mt][nt][1], aux1, aux2);
            epi_store<EPI>(out, i1, acc[mt][nt][2], acc[mt][nt][3], aux1, aux2);
        }
    }
}

// ---------------- WKV chunked scan ------------------------------------------
__global__ __launch_bounds__(256) void wkv_phase_a(
    const float* __restrict__ k, const float* __restrict__ v,
    const float* __restrict__ td, float* __restrict__ Ca, float* __restrict__ Cb)
{
    const int gid = blockIdx.x * blockDim.x + threadIdx.x;   // < NCH*B*C
    const int c  = gid & (Cq - 1);
    const int r  = gid >> 10;
    const int b  = r & (Bq - 1);
    const int ch = r >> 3;
    const float w  = -expf(td[c]);
    const float dw = expf(w);
    const size_t base = ((size_t)(b * Tq + ch * LCH)) * Cq + c;
    float sa = 0.f, sb = 0.f;
    #pragma unroll 4
    for (int i = 0; i < LCH; i++) {
        const float kt = k[base + (size_t)i * Cq];
        const float vt = v[base + (size_t)i * Cq];
        const float ek = __expf(kt);
        sa = fmaf(dw, sa, ek * vt);
        sb = fmaf(dw, sb, ek);
    }
    Ca[gid] = sa; Cb[gid] = sb;
}

__global__ __launch_bounds__(256) void wkv_scan(
    const float* __restrict__ td,
    const float* __restrict__ Ca, const float* __restrict__ Cb,
    float* __restrict__ Sa, float* __restrict__ Sb)
{
    const int sid = blockIdx.x * blockDim.x + threadIdx.x;   // < B*C
    const int c = sid & (Cq - 1);
    const float w  = -expf(td[c]);
    const float dL = expf((float)LCH * w);
    float sa = 0.f, sb = 0.f;
    #pragma unroll
    for (int ch = 0; ch < NCH; ch++) {
        const int idx = ch * (Bq * Cq) + sid;
        Sa[idx] = sa; Sb[idx] = sb;
        sa = fmaf(dL, sa, Ca[idx]);
        sb = fmaf(dL, sb, Cb[idx]);
    }
}

__global__ __launch_bounds__(256) void wkv_phase_b(
    const float* __restrict__ k, const float* __restrict__ v, const float* __restrict__ sr,
    const float* __restrict__ td, const float* __restrict__ tf,
    const float* __restrict__ Sa, const float* __restrict__ Sb, __half* __restrict__ out)
{
    const int gid = blockIdx.x * blockDim.x + threadIdx.x;
    const int c  = gid & (Cq - 1);
    const int r  = gid >> 10;
    const int b  = r & (Bq - 1);
    const int ch = r >> 3;
    const float w  = -expf(td[c]);
    const float dw = expf(w);
    const float eu = expf(tf[c]);
    float a = Sa[gid], bb = Sb[gid];
    const size_t base = ((size_t)(b * Tq + ch * LCH)) * Cq + c;
    #pragma unroll 4
    for (int i = 0; i < LCH; i++) {
        const size_t off = base + (size_t)i * Cq;
        const float kt = k[off];
        const float vt = v[off];
        const float ek = __expf(kt);
        const float euk = eu * ek;
        const float y = (a + euk * vt) / (bb + euk);
        out[off] = __float2half_rn(sr[off] * y);   // feeds Wo GEMM only
        a  = fmaf(dw, a,  ek * vt);
        bb = fmaf(dw, bb, ek);
    }
}

// ---------------- launch -----------------------------------------------------
extern "C" void kernel_launch(void* const* d_in, const int* in_sizes, int n_in,
                              void* d_out, int out_size)
{
    const float* x     = (const float*)d_in[0];
    const float* ln1_g = (const float*)d_in[1];
    const float* ln1_b = (const float*)d_in[2];
    const float* ln2_g = (const float*)d_in[3];
    const float* ln2_b = (const float*)d_in[4];
    const float* td    = (const float*)d_in[5];
    const float* tf    = (const float*)d_in[6];
    const float* tmk   = (const float*)d_in[7];
    const float* tmv   = (const float*)d_in[8];
    const float* tmr   = (const float*)d_in[9];
    const float* Wk    = (const float*)d_in[10];
    const float* Wv    = (const float*)d_in[11];
    const float* Wr    = (const float*)d_in[12];
    const float* Wo    = (const float*)d_in[13];
    const float* fmk   = (const float*)d_in[14];
    const float* fmr   = (const float*)d_in[15];
    const float* Fk    = (const float*)d_in[16];
    const float* Fr    = (const float*)d_in[17];
    const float* Fv    = (const float*)d_in[18];
    float* out = (float*)d_out;

    __half *xk, *xv, *xr, *fk, *fr, *rw, *kk, *wh;
    float *k, *v, *sr, *x1, *sg, *Ca, *Cb, *Sa, *Sb;
    cudaGetSymbolAddress((void**)&xk, g_xk);
    cudaGetSymbolAddress((void**)&xv, g_xv);
    cudaGetSymbolAddress((void**)&xr, g_xr);
    cudaGetSymbolAddress((void**)&fk, g_fk);
    cudaGetSymbolAddress((void**)&fr, g_fr);
    cudaGetSymbolAddress((void**)&rw, g_rw);
    cudaGetSymbolAddress((void**)&kk, g_kk);
    cudaGetSymbolAddress((void**)&wh, g_wh);
    cudaGetSymbolAddress((void**)&k,  g_k);
    cudaGetSymbolAddress((void**)&v,  g_v);
    cudaGetSymbolAddress((void**)&sr, g_sr);
    cudaGetSymbolAddress((void**)&x1, g_x1);
    cudaGetSymbolAddress((void**)&sg, g_sg);
    cudaGetSymbolAddress((void**)&Ca, g_Ca);
    cudaGetSymbolAddress((void**)&Cb, g_Cb);
    cudaGetSymbolAddress((void**)&Sa, g_Sa);
    cudaGetSymbolAddress((void**)&Sb, g_Sb);

    const size_t CC = (size_t)Cq * Cq;          // 1M
    const size_t HC = (size_t)HIDq * Cq;        // 4M
    __half* hWk = wh;
    __half* hWv = wh + CC;
    __half* hWr = wh + 2 * CC;
    __half* hWo = wh + 3 * CC;
    __half* hFr = wh + 4 * CC;
    __half* hFk = wh + 5 * CC;
    __half* hFv = wh + 5 * CC + HC;

    cudaFuncSetAttribute(gemm_f16<0>, cudaFuncAttributeMaxDynamicSharedMemorySize, GEMM_SMEM);
    cudaFuncSetAttribute(gemm_f16<1>, cudaFuncAttributeMaxDynamicSharedMemorySize, GEMM_SMEM);
    cudaFuncSetAttribute(gemm_f16<2>, cudaFuncAttributeMaxDynamicSharedMemorySize, GEMM_SMEM);
    cudaFuncSetAttribute(gemm_f16<3>, cudaFuncAttributeMaxDynamicSharedMemorySize, GEMM_SMEM);
    cudaFuncSetAttribute(gemm_f16<4>, cudaFuncAttributeMaxDynamicSharedMemorySize, GEMM_SMEM);

    // 0,1: weight conversion (batched so ncu -s 5 lands on a GEMM below)
    w2h5<<<dim3((unsigned)(CC / 4 / 256), 5), 256>>>(Wk, Wv, Wr, Wo, Fr, wh);
    w2h2<<<dim3((unsigned)(HC / 4 / 256), 2), 256>>>(Fk, Fv, wh + 5 * CC);

    const dim3 gC(Cq / BN,  Mq / BM);   // (8, 128)   N=1024
    const dim3 gH(HIDq / BN, Mq / BM);  // (32, 128)  N=4096

    // att branch
    ln_mix<3><<<Mq, 256>>>(x, ln1_g, ln1_b, tmk, tmv, tmr, xk, xv, xr);       // 2
    gemm_f16<0><<<gC, 128, GEMM_SMEM>>>(xk, hWk, k,  nullptr, nullptr, Cq, Cq); // 3
    gemm_f16<0><<<gC, 128, GEMM_SMEM>>>(xv, hWv, v,  nullptr, nullptr, Cq, Cq); // 4
    gemm_f16<1><<<gC, 128, GEMM_SMEM>>>(xr, hWr, sr, nullptr, nullptr, Cq, Cq); // 5 <- profiled

    wkv_phase_a<<<(NCH * Bq * Cq) / 256, 256>>>(k, v, td, Ca, Cb);
    wkv_scan   <<<(Bq * Cq) / 256, 256>>>(td, Ca, Cb, Sa, Sb);
    wkv_phase_b<<<(NCH * Bq * Cq) / 256, 256>>>(k, v, sr, td, tf, Sa, Sb, rw);

    gemm_f16<3><<<gC, 128, GEMM_SMEM>>>(rw, hWo, x1, x, nullptr, Cq, Cq);

    // ffn branch
    ln_mix<2><<<Mq, 256>>>(x1, ln2_g, ln2_b, fmk, fmr, nullptr, fk, fr, nullptr);
    gemm_f16<2><<<gH, 128, GEMM_SMEM>>>(fk, hFk, kk, nullptr, nullptr, HIDq, Cq);
    gemm_f16<1><<<gC, 128, GEMM_SMEM>>>(fr, hFr, sg, nullptr, nullptr, Cq, Cq);
    gemm_f16<4><<<gC, 128, GEMM_SMEM>>>(kk, hFv, out, x1, sg, Cq, HIDq);
}

// round 8
// speedup vs baseline: 2.3097x; 1.2172x over previous
#include <cuda_runtime.h>
#include <cuda_fp16.h>
#include <cstdint>

// Problem dims (fixed)
#define Bq   8
#define Tq   2048
#define Cq   1024
#define HIDq 4096
#define Mq   (Bq*Tq)        // 16384 rows
#define NCH  32             // WKV chunks
#define LCH  (Tq/NCH)       // 64 steps per chunk

// GEMM tiling: CTA 128x128 (128 thr), warp 64x64, BK=64 fp16 (128B rows)
#define BM     128
#define BN     128
#define BKK    64
#define STAGES 3
#define ASTGB  (BM*128)              // 16384 bytes per A stage
#define BSTGB  (BN*128)              // 16384 bytes per B stage
#define STGB   (ASTGB + BSTGB)       // 32768 per stage
#define GEMM_SMEM (STAGES*STGB + 1024)   // 99328 -> 2 CTAs/SM

// ---------------- scratch (static device globals; no allocation) ----------
__device__ __half g_xk[(size_t)Mq*Cq];
__device__ __half g_xv[(size_t)Mq*Cq];
__device__ __half g_xr[(size_t)Mq*Cq];
__device__ __half g_fk[(size_t)Mq*Cq];
__device__ __half g_fr[(size_t)Mq*Cq];
__device__ __half g_rw[(size_t)Mq*Cq];
__device__ __half g_kk[(size_t)Mq*HIDq];
__device__ float  g_k [(size_t)Mq*Cq];
__device__ float  g_v [(size_t)Mq*Cq];
__device__ float  g_sr[(size_t)Mq*Cq];
__device__ float  g_x1[(size_t)Mq*Cq];
__device__ float  g_sg[(size_t)Mq*Cq];
__device__ float  g_Ca[(size_t)NCH*Bq*Cq];
__device__ float  g_Cb[(size_t)NCH*Bq*Cq];
__device__ float  g_Sa[(size_t)NCH*Bq*Cq];
__device__ float  g_Sb[(size_t)NCH*Bq*Cq];
// half weights: Wk,Wv,Wr,Wo,Fr (C*C each) then Fk,Fv (HID*C each)
__device__ __half g_wh[(size_t)5*Cq*Cq + (size_t)2*HIDq*Cq];

// ---------------- helpers --------------------------------------------------
__device__ __forceinline__ void mma_f16(float* c, const uint32_t* a, const uint32_t* b) {
    asm volatile(
        "mma.sync.aligned.m16n8k16.row.col.f32.f16.f16.f32 "
        "{%0,%1,%2,%3}, {%4,%5,%6,%7}, {%8,%9}, {%0,%1,%2,%3};"
        : "+f"(c[0]), "+f"(c[1]), "+f"(c[2]), "+f"(c[3])
        : "r"(a[0]), "r"(a[1]), "r"(a[2]), "r"(a[3]), "r"(b[0]), "r"(b[1]));
}
__device__ __forceinline__ void ldsm_x4(uint32_t* d, uint32_t addr) {
    asm volatile("ldmatrix.sync.aligned.m8n8.x4.shared.b16 {%0,%1,%2,%3}, [%4];"
        : "=r"(d[0]), "=r"(d[1]), "=r"(d[2]), "=r"(d[3]) : "r"(addr));
}

__device__ __forceinline__ uint32_t smem_u32(const void* p) {
    uint32_t a;
    asm("{ .reg .u64 t; cvta.to.shared.u64 t, %1; cvt.u32.u64 %0, t; }" : "=r"(a) : "l"(p));
    return a;
}
__device__ __forceinline__ void cp16(uint32_t dst, const void* src) {
    asm volatile("cp.async.cg.shared.global [%0], [%1], 16;" :: "r"(dst), "l"(src));
}
__device__ __forceinline__ void cp_commit() { asm volatile("cp.async.commit_group;"); }
template<int N> __device__ __forceinline__ void cp_wait() {
    asm volatile("cp.async.wait_group %0;" :: "n"(N));
}

// block-wide reduce of 4 values (256 threads)
__device__ __forceinline__ void bred4(float& a, float& b, float& c, float& d) {
    #pragma unroll
    for (int o = 16; o; o >>= 1) {
        a += __shfl_xor_sync(0xffffffffu, a, o);
        b += __shfl_xor_sync(0xffffffffu, b, o);
        c += __shfl_xor_sync(0xffffffffu, c, o);
        d += __shfl_xor_sync(0xffffffffu, d, o);
    }
    __shared__ float sm[8][4];
    int w = threadIdx.x >> 5, l = threadIdx.x & 31;
    if (l == 0) { sm[w][0] = a; sm[w][1] = b; sm[w][2] = c; sm[w][3] = d; }
    __syncthreads();
    a = b = c = d = 0.f;
    #pragma unroll
    for (int j = 0; j < 8; j++) { a += sm[j][0]; b += sm[j][1]; c += sm[j][2]; d += sm[j][3]; }
}

// ---------------- weight conversion fp32 -> fp16 ---------------------------
__global__ __launch_bounds__(256) void w2h5(
    const float* __restrict__ w0, const float* __restrict__ w1, const float* __restrict__ w2,
    const float* __restrict__ w3, const float* __restrict__ w4, __half* __restrict__ dst)
{
    const size_t CC = (size_t)Cq * Cq;
    const float* src = (blockIdx.y == 0) ? w0 : (blockIdx.y == 1) ? w1 :
                       (blockIdx.y == 2) ? w2 : (blockIdx.y == 3) ? w3 : w4;
    __half* d = dst + (size_t)blockIdx.y * CC;
    const int i = blockIdx.x * blockDim.x + threadIdx.x;   // < CC/4
    float4 v = reinterpret_cast<const float4*>(src)[i];
    __half2 h01 = __floats2half2_rn(v.x, v.y);
    __half2 h23 = __floats2half2_rn(v.z, v.w);
    uint2 u; u.x = *reinterpret_cast<uint32_t*>(&h01); u.y = *reinterpret_cast<uint32_t*>(&h23);
    reinterpret_cast<uint2*>(d)[i] = u;
}

__global__ __launch_bounds__(256) void w2h2(
    const float* __restrict__ w0, const float* __restrict__ w1, __half* __restrict__ dst)
{
    const size_t HC = (size_t)HIDq * Cq;
    const float* src = (blockIdx.y == 0) ? w0 : w1;
    __half* d = dst + (size_t)blockIdx.y * HC;
    const int i = blockIdx.x * blockDim.x + threadIdx.x;   // < HC/4
    float4 v = reinterpret_cast<const float4*>(src)[i];
    __half2 h01 = __floats2half2_rn(v.x, v.y);
    __half2 h23 = __floats2half2_rn(v.z, v.w);
    uint2 u; u.x = *reinterpret_cast<uint32_t*>(&h01); u.y = *reinterpret_cast<uint32_t*>(&h23);
    reinterpret_cast<uint2*>(d)[i] = u;
}

// ---------------- fused LayerNorm + time-shift + token-mix (half out) ------
template<int NOUT>
__global__ __launch_bounds__(256) void ln_mix(
    const float* __restrict__ x, const float* __restrict__ g, const float* __restrict__ be,
    const float* __restrict__ m0, const float* __restrict__ m1, const float* __restrict__ m2,
    __half* __restrict__ o0, __half* __restrict__ o1, __half* __restrict__ o2)
{
    const int row = blockIdx.x;          // b*T + t
    const int t   = row & (Tq - 1);
    const int i   = threadIdx.x;         // one float4 per thread (C/4 = 256)

    const float4 v = reinterpret_cast<const float4*>(x + (size_t)row * Cq)[i];
    float4 u = make_float4(0.f, 0.f, 0.f, 0.f);
    if (t > 0) u = reinterpret_cast<const float4*>(x + (size_t)(row - 1) * Cq)[i];

    float s  = v.x + v.y + v.z + v.w;
    float ss = v.x*v.x + v.y*v.y + v.z*v.z + v.w*v.w;
    float sp = u.x + u.y + u.z + u.w;
    float sq = u.x*u.x + u.y*u.y + u.z*u.z + u.w*u.w;
    bred4(s, ss, sp, sq);

    const float inv = 1.f / (float)Cq;
    const float mC = s * inv;
    const float rs = rsqrtf(ss * inv - mC * mC + 1e-5f);
    const float mP = sp * inv;
    const float rp = rsqrtf(sq * inv - mP * mP + 1e-5f);

    const float4 g4 = reinterpret_cast<const float4*>(g)[i];
    const float4 b4 = reinterpret_cast<const float4*>(be)[i];

    float xa[4], xx[4];
    const float* vv = &v.x; const float* uu = &u.x;
    const float* gg = &g4.x; const float* bb = &b4.x;
    #pragma unroll
    for (int j = 0; j < 4; j++) {
        xa[j] = (vv[j] - mC) * rs * gg[j] + bb[j];
        xx[j] = (t > 0) ? ((uu[j] - mP) * rp * gg[j] + bb[j]) : 0.f;
    }

    const size_t oi = (size_t)row * (Cq / 4) + i;
    {
        const float4 w4 = reinterpret_cast<const float4*>(m0)[i];
        const float* ww = &w4.x; float r[4];
        #pragma unroll
        for (int j = 0; j < 4; j++) r[j] = xa[j] * ww[j] + xx[j] * (1.f - ww[j]);
        __half2 h01 = __floats2half2_rn(r[0], r[1]);
        __half2 h23 = __floats2half2_rn(r[2], r[3]);
        uint2 o; o.x = *reinterpret_cast<uint32_t*>(&h01); o.y = *reinterpret_cast<uint32_t*>(&h23);
        reinterpret_cast<uint2*>(o0)[oi] = o;
    }
    {
        const float4 w4 = reinterpret_cast<const float4*>(m1)[i];
        const float* ww = &w4.x; float r[4];
        #pragma unroll
        for (int j = 0; j < 4; j++) r[j] = xa[j] * ww[j] + xx[j] * (1.f - ww[j]);
        __half2 h01 = __floats2half2_rn(r[0], r[1]);
        __half2 h23 = __floats2half2_rn(r[2], r[3]);
        uint2 o; o.x = *reinterpret_cast<uint32_t*>(&h01); o.y = *reinterpret_cast<uint32_t*>(&h23);
        reinterpret_cast<uint2*>(o1)[oi] = o;
    }
    if (NOUT == 3) {
        const float4 w4 = reinterpret_cast<const float4*>(m2)[i];
        const float* ww = &w4.x; float r[4];
        #pragma unroll
        for (int j = 0; j < 4; j++) r[j] = xa[j] * ww[j] + xx[j] * (1.f - ww[j]);
        __half2 h01 = __floats2half2_rn(r[0], r[1]);
        __half2 h23 = __floats2half2_rn(r[2], r[3]);
        uint2 o; o.x = *reinterpret_cast<uint32_t*>(&h01); o.y = *reinterpret_cast<uint32_t*>(&h23);
        reinterpret_cast<uint2*>(o2)[oi] = o;
    }
}

// ---------------- fp16 GEMM, 128x128 tile, 4 warps @ 64x64, ldmatrix -------
// out[m,n] = sum_k A[m,k]*W[n,k], A/W half, accumulate fp32 in MMA.
// Smem: XOR-swizzled 128B rows: addr = base + row*128 + (col ^ ((row&7)*16)).
// Fragments via ldmatrix.x4. 2 CTAs/SM.
// EPI: 0 none(f32) | 1 sigmoid(f32) | 2 relu^2 -> HALF out | 3 aux1+acc | 4 aux1+aux2*acc

__device__ __forceinline__ void fill_tile(uint32_t sbase, int stage,
    const __half* __restrict__ Ag, const __half* __restrict__ Wg, int K, int k0, int tid)
{
    const uint32_t sa = sbase + (uint32_t)stage * STGB;
    #pragma unroll
    for (int p = 0; p < 8; p++) {            // A: 128 rows x 8 chunks = 1024
        const int id  = tid + p * 128;
        const int row = id >> 3, c = id & 7;
        const uint32_t off = (uint32_t)(row * 128 + c * 16);
        cp16(sa + (off ^ ((off >> 3) & 0x70)), Ag + (size_t)row * K + k0 + c * 8);
    }
    const uint32_t sb = sa + ASTGB;
    #pragma unroll
    for (int p = 0; p < 8; p++) {            // B: 128 rows x 8 chunks = 1024
        const int id  = tid + p * 128;
        const int row = id >> 3, c = id & 7;
        const uint32_t off = (uint32_t)(row * 128 + c * 16);
        cp16(sb + (off ^ ((off >> 3) & 0x70)), Wg + (size_t)row * K + k0 + c * 8);
    }
}

template<int EPI>
__device__ __forceinline__ void epi_store(void* __restrict__ out, size_t idx,
    float c0, float c1, const float* __restrict__ a1, const float* __restrict__ a2)
{
    if (EPI == 2) {
        c0 = fmaxf(c0, 0.f); c0 *= c0;
        c1 = fmaxf(c1, 0.f); c1 *= c1;
        __half2 h = __floats2half2_rn(c0, c1);
        *reinterpret_cast<__half2*>((__half*)out + idx) = h;
        return;
    }
    if (EPI == 1) { c0 = 1.f / (1.f + __expf(-c0)); c1 = 1.f / (1.f + __expf(-c1)); }
    else if (EPI == 3) { c0 += a1[idx]; c1 += a1[idx + 1]; }
    else if (EPI == 4) { c0 = a1[idx] + a2[idx] * c0; c1 = a1[idx + 1] + a2[idx + 1] * c1; }
    float2 t; t.x = c0; t.y = c1;
    *reinterpret_cast<float2*>((float*)out + idx) = t;
}

template<int EPI>
__global__ __launch_bounds__(128, 2) void gemm_f16(
    const __half* __restrict__ A, const __half* __restrict__ W, void* __restrict__ out,
    const float* __restrict__ aux1, const float* __restrict__ aux2, int N, int K)
{
    extern __shared__ float dsm[];
    const uint32_t sbase = (smem_u32(dsm) + 1023u) & ~1023u;

    const int tid  = threadIdx.x;
    const int lane = tid & 31;
    const int warp = tid >> 5;
    const int wm   = warp >> 1;   // 0..1 -> 64 rows each
    const int wn   = warp & 1;    // 0..1 -> 64 cols each

    const int brow = blockIdx.y * BM;
    const int bcol = blockIdx.x * BN;
    const __half* Ag = A + (size_t)brow * K;
    const __half* Wg = W + (size_t)bcol * K;
    const int ntiles = K / BKK;

    // ldmatrix lane mapping: g = lane/8 selects the 8x8 matrix this lane
    // addresses; r = lane%8 is the row within it.
    // A x4 matrices (d0..d3): (m0-7,k0-7),(m8-15,k0-7),(m0-7,k8-15),(m8-15,k8-15)
    //   -> m-half = g&1, k-half = g>>1
    // B x4 matrices: (n0-7,k0-7),(n0-7,k8-15),(n8-15,k0-7),(n8-15,k8-15)
    //   -> n-half = g>>1, k-half = g&1
    const int g = lane >> 3, r = lane & 7;
    const uint32_t colA = (uint32_t)((g >> 1) * 16);   // k-half byte offset
    const uint32_t colB = (uint32_t)((g & 1) * 16);
    uint32_t arow128[4], axor[4];
    #pragma unroll
    for (int mt = 0; mt < 4; mt++) {
        const int row = wm * 64 + mt * 16 + (g & 1) * 8 + r;
        arow128[mt] = (uint32_t)(row * 128);
        axor[mt]    = (uint32_t)((row & 7) * 16);
    }
    uint32_t brow128[4], bxor[4];
    #pragma unroll
    for (int p = 0; p < 4; p++) {
        const int row = wn * 64 + p * 16 + (g >> 1) * 8 + r;
        brow128[p] = (uint32_t)(row * 128);
        bxor[p]    = (uint32_t)((row & 7) * 16);
    }

    // prologue
    fill_tile(sbase, 0, Ag, Wg, K, 0,   tid); cp_commit();
    fill_tile(sbase, 1, Ag, Wg, K, BKK, tid); cp_commit();

    float acc[4][8][4];
    #pragma unroll
    for (int mt = 0; mt < 4; mt++)
        #pragma unroll
        for (int nt = 0; nt < 8; nt++)
            #pragma unroll
            for (int q = 0; q < 4; q++) acc[mt][nt][q] = 0.f;

    for (int t = 0; t < ntiles; t++) {
        cp_wait<STAGES - 2>();
        __syncthreads();

        const int tp = t + STAGES - 1;
        if (tp < ntiles) fill_tile(sbase, tp % STAGES, Ag, Wg, K, tp * BKK, tid);
        cp_commit();

        const uint32_t sA = sbase + (uint32_t)(t % STAGES) * STGB;
        const uint32_t sB = sA + ASTGB;

        #pragma unroll
        for (int ks = 0; ks < 4; ks++) {      // 4 x k16 = K64
            const uint32_t cb = (uint32_t)(ks * 32);   // k16 step = 32 bytes
            uint32_t a[4][4], b[4][4];
            #pragma unroll
            for (int mt = 0; mt < 4; mt++)
                ldsm_x4(a[mt], sA + arow128[mt] + ((colA + cb) ^ axor[mt]));
            #pragma unroll
            for (int p = 0; p < 4; p++)
                ldsm_x4(b[p], sB + brow128[p] + ((colB + cb) ^ bxor[p]));
            #pragma unroll
            for (int mt = 0; mt < 4; mt++)
                #pragma unroll
                for (int nt = 0; nt < 8; nt++)
                    mma_f16(acc[mt][nt], a[mt], &b[nt >> 1][(nt & 1) * 2]);
        }
        __syncthreads();
    }

    // epilogue straight from registers
    const int qrow = lane >> 2, qcol = lane & 3;
    #pragma unroll
    for (int mt = 0; mt < 4; mt++) {
        #pragma unroll
        for (int nt = 0; nt < 8; nt++) {
            const int row = brow + wm * 64 + mt * 16 + qrow;
            const int col = bcol + wn * 64 + nt * 8 + qcol * 2;
            const size_t i0 = (size_t)row * N + col;
            const size_t i1 = (size_t)(row + 8) * N + col;
            epi_store<EPI>(out, i0, acc[mt][nt][0], acc[mt][nt][1], aux1, aux2);
            epi_store<EPI>(out, i1, acc[mt][nt][2], acc[mt][nt][3], aux1, aux2);
        }
    }
}

// ---------------- WKV chunked scan ------------------------------------------
__global__ __launch_bounds__(256) void wkv_phase_a(
    const float* __restrict__ k, const float* __restrict__ v,
    const float* __restrict__ td, float* __restrict__ Ca, float* __restrict__ Cb)
{
    const int gid = blockIdx.x * blockDim.x + threadIdx.x;   // < NCH*B*C
    const int c  = gid & (Cq - 1);
    const int r  = gid >> 10;
    const int b  = r & (Bq - 1);
    const int ch = r >> 3;
    const float w  = -expf(td[c]);
    const float dw = expf(w);
    const size_t base = ((size_t)(b * Tq + ch * LCH)) * Cq + c;
    float sa = 0.f, sb = 0.f;
    #pragma unroll 4
    for (int i = 0; i < LCH; i++) {
        const float kt = k[base + (size_t)i * Cq];
        const float vt = v[base + (size_t)i * Cq];
        const float ek = __expf(kt);
        sa = fmaf(dw, sa, ek * vt);
        sb = fmaf(dw, sb, ek);
    }
    Ca[gid] = sa; Cb[gid] = sb;
}

__global__ __launch_bounds__(256) void wkv_scan(
    const float* __restrict__ td,
    const float* __restrict__ Ca, const float* __restrict__ Cb,
    float* __restrict__ Sa, float* __restrict__ Sb)
{
    const int sid = blockIdx.x * blockDim.x + threadIdx.x;   // < B*C
    const int c = sid & (Cq - 1);
    const float w  = -expf(td[c]);
    const float dL = expf((float)LCH * w);
    float sa = 0.f, sb = 0.f;
    #pragma unroll
    for (int ch = 0; ch < NCH; ch++) {
        const int idx = ch * (Bq * Cq) + sid;
        Sa[idx] = sa; Sb[idx] = sb;
        sa = fmaf(dL, sa, Ca[idx]);
        sb = fmaf(dL, sb, Cb[idx]);
    }
}

__global__ __launch_bounds__(256) void wkv_phase_b(
    const float* __restrict__ k, const float* __restrict__ v, const float* __restrict__ sr,
    const float* __restrict__ td, const float* __restrict__ tf,
    const float* __restrict__ Sa, const float* __restrict__ Sb, __half* __restrict__ out)
{
    const int gid = blockIdx.x * blockDim.x + threadIdx.x;
    const int c  = gid & (Cq - 1);
    const int r  = gid >> 10;
    const int b  = r & (Bq - 1);
    const int ch = r >> 3;
    const float w  = -expf(td[c]);
    const float dw = expf(w);
    const float eu = expf(tf[c]);
    float a = Sa[gid], bb = Sb[gid];
    const size_t base = ((size_t)(b * Tq + ch * LCH)) * Cq + c;
    #pragma unroll 4
    for (int i = 0; i < LCH; i++) {
        const size_t off = base + (size_t)i * Cq;
        const float kt = k[off];
        const float vt = v[off];
        const float ek = __expf(kt);
        const float euk = eu * ek;
        const float y = (a + euk * vt) / (bb + euk);
        out[off] = __float2half_rn(sr[off] * y);   // feeds Wo GEMM only
        a  = fmaf(dw, a,  ek * vt);
        bb = fmaf(dw, bb, ek);
    }
}

// ---------------- launch -----------------------------------------------------
extern "C" void kernel_launch(void* const* d_in, const int* in_sizes, int n_in,
                              void* d_out, int out_size)
{
    const float* x     = (const float*)d_in[0];
    const float* ln1_g = (const float*)d_in[1];
    const float* ln1_b = (const float*)d_in[2];
    const float* ln2_g = (const float*)d_in[3];
    const float* ln2_b = (const float*)d_in[4];
    const float* td    = (const float*)d_in[5];
    const float* tf    = (const float*)d_in[6];
    const float* tmk   = (const float*)d_in[7];
    const float* tmv   = (const float*)d_in[8];
    const float* tmr   = (const float*)d_in[9];
    const float* Wk    = (const float*)d_in[10];
    const float* Wv    = (const float*)d_in[11];
    const float* Wr    = (const float*)d_in[12];
    const float* Wo    = (const float*)d_in[13];
    const float* fmk   = (const float*)d_in[14];
    const float* fmr   = (const float*)d_in[15];
    const float* Fk    = (const float*)d_in[16];
    const float* Fr    = (const float*)d_in[17];
    const float* Fv    = (const float*)d_in[18];
    float* out = (float*)d_out;

    __half *xk, *xv, *xr, *fk, *fr, *rw, *kk, *wh;
    float *k, *v, *sr, *x1, *sg, *Ca, *Cb, *Sa, *Sb;
    cudaGetSymbolAddress((void**)&xk, g_xk);
    cudaGetSymbolAddress((void**)&xv, g_xv);
    cudaGetSymbolAddress((void**)&xr, g_xr);
    cudaGetSymbolAddress((void**)&fk, g_fk);
    cudaGetSymbolAddress((void**)&fr, g_fr);
    cudaGetSymbolAddress((void**)&rw, g_rw);
    cudaGetSymbolAddress((void**)&kk, g_kk);
    cudaGetSymbolAddress((void**)&wh, g_wh);
    cudaGetSymbolAddress((void**)&k,  g_k);
    cudaGetSymbolAddress((void**)&v,  g_v);
    cudaGetSymbolAddress((void**)&sr, g_sr);
    cudaGetSymbolAddress((void**)&x1, g_x1);
    cudaGetSymbolAddress((void**)&sg, g_sg);
    cudaGetSymbolAddress((void**)&Ca, g_Ca);
    cudaGetSymbolAddress((void**)&Cb, g_Cb);
    cudaGetSymbolAddress((void**)&Sa, g_Sa);
    cudaGetSymbolAddress((void**)&Sb, g_Sb);

    const size_t CC = (size_t)Cq * Cq;          // 1M
    const size_t HC = (size_t)HIDq * Cq;        // 4M
    __half* hWk = wh;
    __half* hWv = wh + CC;
    __half* hWr = wh + 2 * CC;
    __half* hWo = wh + 3 * CC;
    __half* hFr = wh + 4 * CC;
    __half* hFk = wh + 5 * CC;
    __half* hFv = wh + 5 * CC + HC;

    cudaFuncSetAttribute(gemm_f16<0>, cudaFuncAttributeMaxDynamicSharedMemorySize, GEMM_SMEM);
    cudaFuncSetAttribute(gemm_f16<1>, cudaFuncAttributeMaxDynamicSharedMemorySize, GEMM_SMEM);
    cudaFuncSetAttribute(gemm_f16<2>, cudaFuncAttributeMaxDynamicSharedMemorySize, GEMM_SMEM);
    cudaFuncSetAttribute(gemm_f16<3>, cudaFuncAttributeMaxDynamicSharedMemorySize, GEMM_SMEM);
    cudaFuncSetAttribute(gemm_f16<4>, cudaFuncAttributeMaxDynamicSharedMemorySize, GEMM_SMEM);

    // 0,1: weight conversion (batched so ncu -s 5 lands on a GEMM below)
    w2h5<<<dim3((unsigned)(CC / 4 / 256), 5), 256>>>(Wk, Wv, Wr, Wo, Fr, wh);
    w2h2<<<dim3((unsigned)(HC / 4 / 256), 2), 256>>>(Fk, Fv, wh + 5 * CC);

    const dim3 gC(Cq / BN,  Mq / BM);   // (8, 128)   N=1024
    const dim3 gH(HIDq / BN, Mq / BM);  // (32, 128)  N=4096

    // att branch
    ln_mix<3><<<Mq, 256>>>(x, ln1_g, ln1_b, tmk, tmv, tmr, xk, xv, xr);       // 2
    gemm_f16<0><<<gC, 128, GEMM_SMEM>>>(xk, hWk, k,  nullptr, nullptr, Cq, Cq); // 3
    gemm_f16<0><<<gC, 128, GEMM_SMEM>>>(xv, hWv, v,  nullptr, nullptr, Cq, Cq); // 4
    gemm_f16<1><<<gC, 128, GEMM_SMEM>>>(xr, hWr, sr, nullptr, nullptr, Cq, Cq); // 5 <- profiled

    wkv_phase_a<<<(NCH * Bq * Cq) / 256, 256>>>(k, v, td, Ca, Cb);
    wkv_scan   <<<(Bq * Cq) / 256, 256>>>(td, Ca, Cb, Sa, Sb);
    wkv_phase_b<<<(NCH * Bq * Cq) / 256, 256>>>(k, v, sr, td, tf, Sa, Sb, rw);

    gemm_f16<3><<<gC, 128, GEMM_SMEM>>>(rw, hWo, x1, x, nullptr, Cq, Cq);

    // ffn branch
    ln_mix<2><<<Mq, 256>>>(x1, ln2_g, ln2_b, fmk, fmr, nullptr, fk, fr, nullptr);
    gemm_f16<2><<<gH, 128, GEMM_SMEM>>>(fk, hFk, kk, nullptr, nullptr, HIDq, Cq);
    gemm_f16<1><<<gC, 128, GEMM_SMEM>>>(fr, hFr, sg, nullptr, nullptr, Cq, Cq);
    gemm_f16<4><<<gC, 128, GEMM_SMEM>>>(kk, hFv, out, x1, sg, Cq, HIDq);
}

// round 9
// speedup vs baseline: 2.3709x; 1.0265x over previous
#include <cuda_runtime.h>
#include <cuda_fp16.h>
#include <cstdint>

// Problem dims (fixed)
#define Bq   8
#define Tq   2048
#define Cq   1024
#define HIDq 4096
#define Mq   (Bq*Tq)        // 16384 rows
#define NCH  32             // WKV chunks
#define LCH  (Tq/NCH)       // 64 steps per chunk

// GEMM tiling: CTA 128x128 (128 thr), warp 64x64, BK=64 fp16 (128B rows)
#define BM     128
#define BN     128
#define BKK    64
#define STAGES 3
#define ASTGB  (BM*128)              // 16384 bytes per A stage
#define BSTGB  (BN*128)              // 16384 bytes per B stage
#define STGB   (ASTGB + BSTGB)       // 32768 per stage
#define GEMM_SMEM (STAGES*STGB + 1024)   // 99328 -> 2 CTAs/SM

// ---------------- scratch (static device globals; no allocation) ----------
__device__ __half g_xk[(size_t)Mq*Cq];
__device__ __half g_xv[(size_t)Mq*Cq];
__device__ __half g_xr[(size_t)Mq*Cq];
__device__ __half g_fk[(size_t)Mq*Cq];
__device__ __half g_fr[(size_t)Mq*Cq];
__device__ __half g_rw[(size_t)Mq*Cq];
__device__ __half g_kk[(size_t)Mq*HIDq];
__device__ float  g_k [(size_t)Mq*Cq];
__device__ float  g_v [(size_t)Mq*Cq];
__device__ float  g_sr[(size_t)Mq*Cq];
__device__ float  g_x1[(size_t)Mq*Cq];
__device__ float  g_sg[(size_t)Mq*Cq];
__device__ float  g_Ca[(size_t)NCH*Bq*Cq];
__device__ float  g_Cb[(size_t)NCH*Bq*Cq];
__device__ float  g_Sa[(size_t)NCH*Bq*Cq];
__device__ float  g_Sb[(size_t)NCH*Bq*Cq];
// half weights: Wk,Wv,Wr,Wo,Fr (C*C each) then Fk,Fv (HID*C each)
__device__ __half g_wh[(size_t)5*Cq*Cq + (size_t)2*HIDq*Cq];

// ---------------- helpers --------------------------------------------------
__device__ __forceinline__ void mma_f16(float* c, const uint32_t* a, const uint32_t* b) {
    asm volatile(
        "mma.sync.aligned.m16n8k16.row.col.f32.f16.f16.f32 "
        "{%0,%1,%2,%3}, {%4,%5,%6,%7}, {%8,%9}, {%0,%1,%2,%3};"
        : "+f"(c[0]), "+f"(c[1]), "+f"(c[2]), "+f"(c[3])
        : "r"(a[0]), "r"(a[1]), "r"(a[2]), "r"(a[3]), "r"(b[0]), "r"(b[1]));
}
__device__ __forceinline__ void ldsm_x4(uint32_t* d, uint32_t addr) {
    asm volatile("ldmatrix.sync.aligned.m8n8.x4.shared.b16 {%0,%1,%2,%3}, [%4];"
        : "=r"(d[0]), "=r"(d[1]), "=r"(d[2]), "=r"(d[3]) : "r"(addr));
}

__device__ __forceinline__ uint32_t smem_u32(const void* p) {
    uint32_t a;
    asm("{ .reg .u64 t; cvta.to.shared.u64 t, %1; cvt.u32.u64 %0, t; }" : "=r"(a) : "l"(p));
    return a;
}
__device__ __forceinline__ void cp16(uint32_t dst, const void* src) {
    asm volatile("cp.async.cg.shared.global [%0], [%1], 16;" :: "r"(dst), "l"(src));
}
__device__ __forceinline__ void cp_commit() { asm volatile("cp.async.commit_group;"); }
template<int N> __device__ __forceinline__ void cp_wait() {
    asm volatile("cp.async.wait_group %0;" :: "n"(N));
}

// block-wide reduce of 4 values (256 threads)
__device__ __forceinline__ void bred4(float& a, float& b, float& c, float& d) {
    #pragma unroll
    for (int o = 16; o; o >>= 1) {
        a += __shfl_xor_sync(0xffffffffu, a, o);
        b += __shfl_xor_sync(0xffffffffu, b, o);
        c += __shfl_xor_sync(0xffffffffu, c, o);
        d += __shfl_xor_sync(0xffffffffu, d, o);
    }
    __shared__ float sm[8][4];
    int w = threadIdx.x >> 5, l = threadIdx.x & 31;
    if (l == 0) { sm[w][0] = a; sm[w][1] = b; sm[w][2] = c; sm[w][3] = d; }
    __syncthreads();
    a = b = c = d = 0.f;
    #pragma unroll
    for (int j = 0; j < 8; j++) { a += sm[j][0]; b += sm[j][1]; c += sm[j][2]; d += sm[j][3]; }
}

// ---------------- weight conversion fp32 -> fp16 ---------------------------
__global__ __launch_bounds__(256) void w2h5(
    const float* __restrict__ w0, const float* __restrict__ w1, const float* __restrict__ w2,
    const float* __restrict__ w3, const float* __restrict__ w4, __half* __restrict__ dst)
{
    const size_t CC = (size_t)Cq * Cq;
    const float* src = (blockIdx.y == 0) ? w0 : (blockIdx.y == 1) ? w1 :
                       (blockIdx.y == 2) ? w2 : (blockIdx.y == 3) ? w3 : w4;
    __half* d = dst + (size_t)blockIdx.y * CC;
    const int i = blockIdx.x * blockDim.x + threadIdx.x;   // < CC/4
    float4 v = reinterpret_cast<const float4*>(src)[i];
    __half2 h01 = __floats2half2_rn(v.x, v.y);
    __half2 h23 = __floats2half2_rn(v.z, v.w);
    uint2 u; u.x = *reinterpret_cast<uint32_t*>(&h01); u.y = *reinterpret_cast<uint32_t*>(&h23);
    reinterpret_cast<uint2*>(d)[i] = u;
}

__global__ __launch_bounds__(256) void w2h2(
    const float* __restrict__ w0, const float* __restrict__ w1, __half* __restrict__ dst)
{
    const size_t HC = (size_t)HIDq * Cq;
    const float* src = (blockIdx.y == 0) ? w0 : w1;
    __half* d = dst + (size_t)blockIdx.y * HC;
    const int i = blockIdx.x * blockDim.x + threadIdx.x;   // < HC/4
    float4 v = reinterpret_cast<const float4*>(src)[i];
    __half2 h01 = __floats2half2_rn(v.x, v.y);
    __half2 h23 = __floats2half2_rn(v.z, v.w);
    uint2 u; u.x = *reinterpret_cast<uint32_t*>(&h01); u.y = *reinterpret_cast<uint32_t*>(&h23);
    reinterpret_cast<uint2*>(d)[i] = u;
}

// ---------------- fused LayerNorm + time-shift + token-mix (half out) ------
template<int NOUT>
__global__ __launch_bounds__(256) void ln_mix(
    const float* __restrict__ x, const float* __restrict__ g, const float* __restrict__ be,
    const float* __restrict__ m0, const float* __restrict__ m1, const float* __restrict__ m2,
    __half* __restrict__ o0, __half* __restrict__ o1, __half* __restrict__ o2)
{
    const int row = blockIdx.x;          // b*T + t
    const int t   = row & (Tq - 1);
    const int i   = threadIdx.x;         // one float4 per thread (C/4 = 256)

    const float4 v = reinterpret_cast<const float4*>(x + (size_t)row * Cq)[i];
    float4 u = make_float4(0.f, 0.f, 0.f, 0.f);
    if (t > 0) u = reinterpret_cast<const float4*>(x + (size_t)(row - 1) * Cq)[i];

    float s  = v.x + v.y + v.z + v.w;
    float ss = v.x*v.x + v.y*v.y + v.z*v.z + v.w*v.w;
    float sp = u.x + u.y + u.z + u.w;
    float sq = u.x*u.x + u.y*u.y + u.z*u.z + u.w*u.w;
    bred4(s, ss, sp, sq);

    const float inv = 1.f / (float)Cq;
    const float mC = s * inv;
    const float rs = rsqrtf(ss * inv - mC * mC + 1e-5f);
    const float mP = sp * inv;
    const float rp = rsqrtf(sq * inv - mP * mP + 1e-5f);

    const float4 g4 = reinterpret_cast<const float4*>(g)[i];
    const float4 b4 = reinterpret_cast<const float4*>(be)[i];

    float xa[4], xx[4];
    const float* vv = &v.x; const float* uu = &u.x;
    const float* gg = &g4.x; const float* bb = &b4.x;
    #pragma unroll
    for (int j = 0; j < 4; j++) {
        xa[j] = (vv[j] - mC) * rs * gg[j] + bb[j];
        xx[j] = (t > 0) ? ((uu[j] - mP) * rp * gg[j] + bb[j]) : 0.f;
    }

    const size_t oi = (size_t)row * (Cq / 4) + i;
    {
        const float4 w4 = reinterpret_cast<const float4*>(m0)[i];
        const float* ww = &w4.x; float r[4];
        #pragma unroll
        for (int j = 0; j < 4; j++) r[j] = xa[j] * ww[j] + xx[j] * (1.f - ww[j]);
        __half2 h01 = __floats2half2_rn(r[0], r[1]);
        __half2 h23 = __floats2half2_rn(r[2], r[3]);
        uint2 o; o.x = *reinterpret_cast<uint32_t*>(&h01); o.y = *reinterpret_cast<uint32_t*>(&h23);
        reinterpret_cast<uint2*>(o0)[oi] = o;
    }
    {
        const float4 w4 = reinterpret_cast<const float4*>(m1)[i];
        const float* ww = &w4.x; float r[4];
        #pragma unroll
        for (int j = 0; j < 4; j++) r[j] = xa[j] * ww[j] + xx[j] * (1.f - ww[j]);
        __half2 h01 = __floats2half2_rn(r[0], r[1]);
        __half2 h23 = __floats2half2_rn(r[2], r[3]);
        uint2 o; o.x = *reinterpret_cast<uint32_t*>(&h01); o.y = *reinterpret_cast<uint32_t*>(&h23);
        reinterpret_cast<uint2*>(o1)[oi] = o;
    }
    if (NOUT == 3) {
        const float4 w4 = reinterpret_cast<const float4*>(m2)[i];
        const float* ww = &w4.x; float r[4];
        #pragma unroll
        for (int j = 0; j < 4; j++) r[j] = xa[j] * ww[j] + xx[j] * (1.f - ww[j]);
        __half2 h01 = __floats2half2_rn(r[0], r[1]);
        __half2 h23 = __floats2half2_rn(r[2], r[3]);
        uint2 o; o.x = *reinterpret_cast<uint32_t*>(&h01); o.y = *reinterpret_cast<uint32_t*>(&h23);
        reinterpret_cast<uint2*>(o2)[oi] = o;
    }
}

// ---------------- fp16 GEMM core, 128x128 tile, 4 warps @ 64x64, ldmatrix --
// 3-stage cp.async ring, prefetch distance 1, ONE __syncthreads per tile.
// Safety: max warp skew between barriers is {fill(t+2), compute(t)} ->
// stages (t+2)%3 vs t%3, always distinct.
// EPI: 0 none(f32) | 1 sigmoid(f32) | 2 relu^2 -> HALF out | 3 aux1+acc | 4 aux1+aux2*acc

__device__ __forceinline__ void fill_tile(uint32_t sbase, int stage,
    const __half* __restrict__ Ag, const __half* __restrict__ Wg, int K, int k0, int tid)
{
    const uint32_t sa = sbase + (uint32_t)stage * STGB;
    #pragma unroll
    for (int p = 0; p < 8; p++) {            // A: 128 rows x 8 chunks = 1024
        const int id  = tid + p * 128;
        const int row = id >> 3, c = id & 7;
        const uint32_t off = (uint32_t)(row * 128 + c * 16);
        cp16(sa + (off ^ ((off >> 3) & 0x70)), Ag + (size_t)row * K + k0 + c * 8);
    }
    const uint32_t sb = sa + ASTGB;
    #pragma unroll
    for (int p = 0; p < 8; p++) {            // B: 128 rows x 8 chunks = 1024
        const int id  = tid + p * 128;
        const int row = id >> 3, c = id & 7;
        const uint32_t off = (uint32_t)(row * 128 + c * 16);
        cp16(sb + (off ^ ((off >> 3) & 0x70)), Wg + (size_t)row * K + k0 + c * 8);
    }
}

template<int EPI>
__device__ __forceinline__ void epi_store(void* __restrict__ out, size_t idx,
    float c0, float c1, const float* __restrict__ a1, const float* __restrict__ a2)
{
    if (EPI == 2) {
        c0 = fmaxf(c0, 0.f); c0 *= c0;
        c1 = fmaxf(c1, 0.f); c1 *= c1;
        __half2 h = __floats2half2_rn(c0, c1);
        *reinterpret_cast<__half2*>((__half*)out + idx) = h;
        return;
    }
    if (EPI == 1) { c0 = 1.f / (1.f + __expf(-c0)); c1 = 1.f / (1.f + __expf(-c1)); }
    else if (EPI == 3) { c0 += a1[idx]; c1 += a1[idx + 1]; }
    else if (EPI == 4) { c0 = a1[idx] + a2[idx] * c0; c1 = a1[idx + 1] + a2[idx + 1] * c1; }
    float2 t; t.x = c0; t.y = c1;
    *reinterpret_cast<float2*>((float*)out + idx) = t;
}

template<int EPI>
__device__ __forceinline__ void gemm_body(
    const __half* __restrict__ A, const __half* __restrict__ W, void* __restrict__ out,
    const float* __restrict__ aux1, const float* __restrict__ aux2, int N, int K,
    uint32_t sbase)
{
    const int tid  = threadIdx.x;
    const int lane = tid & 31;
    const int warp = tid >> 5;
    const int wm   = warp >> 1;   // 0..1 -> 64 rows each
    const int wn   = warp & 1;    // 0..1 -> 64 cols each

    const int brow = blockIdx.y * BM;
    const int bcol = blockIdx.x * BN;
    const __half* Ag = A + (size_t)brow * K;
    const __half* Wg = W + (size_t)bcol * K;
    const int ntiles = K / BKK;

    // ldmatrix lane mapping (see round-8 comments)
    const int g = lane >> 3, r = lane & 7;
    const uint32_t colA = (uint32_t)((g >> 1) * 16);
    const uint32_t colB = (uint32_t)((g & 1) * 16);
    uint32_t arow128[4], axor[4];
    #pragma unroll
    for (int mt = 0; mt < 4; mt++) {
        const int row = wm * 64 + mt * 16 + (g & 1) * 8 + r;
        arow128[mt] = (uint32_t)(row * 128);
        axor[mt]    = (uint32_t)((row & 7) * 16);
    }
    uint32_t brow128[4], bxor[4];
    #pragma unroll
    for (int p = 0; p < 4; p++) {
        const int row = wn * 64 + p * 16 + (g >> 1) * 8 + r;
        brow128[p] = (uint32_t)(row * 128);
        bxor[p]    = (uint32_t)((row & 7) * 16);
    }

    // prologue: 1 tile in flight (prefetch distance 1)
    fill_tile(sbase, 0, Ag, Wg, K, 0, tid); cp_commit();

    float acc[4][8][4];
    #pragma unroll
    for (int mt = 0; mt < 4; mt++)
        #pragma unroll
        for (int nt = 0; nt < 8; nt++)
            #pragma unroll
            for (int q = 0; q < 4; q++) acc[mt][nt][q] = 0.f;

    for (int t = 0; t < ntiles; t++) {
        const int tp = t + 1;
        if (tp < ntiles) fill_tile(sbase, tp % STAGES, Ag, Wg, K, tp * BKK, tid);
        cp_commit();                       // unconditional (empty group on last iter)
        cp_wait<1>();                      // stage t complete
        __syncthreads();                   // the ONLY barrier per tile

        const uint32_t sA = sbase + (uint32_t)(t % STAGES) * STGB;
        const uint32_t sB = sA + ASTGB;

        #pragma unroll
        for (int ks = 0; ks < 4; ks++) {
            const uint32_t cb = (uint32_t)(ks * 32);
            uint32_t a[4][4], b[4][4];
            #pragma unroll
            for (int mt = 0; mt < 4; mt++)
                ldsm_x4(a[mt], sA + arow128[mt] + ((colA + cb) ^ axor[mt]));
            #pragma unroll
            for (int p = 0; p < 4; p++)
                ldsm_x4(b[p], sB + brow128[p] + ((colB + cb) ^ bxor[p]));
            #pragma unroll
            for (int mt = 0; mt < 4; mt++)
                #pragma unroll
                for (int nt = 0; nt < 8; nt++)
                    mma_f16(acc[mt][nt], a[mt], &b[nt >> 1][(nt & 1) * 2]);
        }
    }

    // epilogue straight from registers
    const int qrow = lane >> 2, qcol = lane & 3;
    #pragma unroll
    for (int mt = 0; mt < 4; mt++) {
        #pragma unroll
        for (int nt = 0; nt < 8; nt++) {
            const int row = brow + wm * 64 + mt * 16 + qrow;
            const int col = bcol + wn * 64 + nt * 8 + qcol * 2;
            const size_t i0 = (size_t)row * N + col;
            const size_t i1 = (size_t)(row + 8) * N + col;
            epi_store<EPI>(out, i0, acc[mt][nt][0], acc[mt][nt][1], aux1, aux2);
            epi_store<EPI>(out, i1, acc[mt][nt][2], acc[mt][nt][3], aux1, aux2);
        }
    }
}

template<int EPI>
__global__ __launch_bounds__(128, 2) void gemm_f16(
    const __half* __restrict__ A, const __half* __restrict__ W, void* __restrict__ out,
    const float* __restrict__ aux1, const float* __restrict__ aux2, int N, int K)
{
    extern __shared__ float dsm[];
    const uint32_t sbase = (smem_u32(dsm) + 1023u) & ~1023u;
    gemm_body<EPI>(A, W, out, aux1, aux2, N, K, sbase);
}

// merged k & v GEMMs (same EPI=0): z selects operand set; 2x wave depth -> less tail
__global__ __launch_bounds__(128, 2) void gemm_kv(
    const __half* __restrict__ xk, const __half* __restrict__ xv,
    const __half* __restrict__ wk, const __half* __restrict__ wv,
    float* __restrict__ k, float* __restrict__ v, int N, int K)
{
    extern __shared__ float dsm[];
    const uint32_t sbase = (smem_u32(dsm) + 1023u) & ~1023u;
    const bool z = (blockIdx.z != 0);
    gemm_body<0>(z ? xv : xk, z ? wv : wk, z ? (void*)v : (void*)k,
                 nullptr, nullptr, N, K, sbase);
}

// ---------------- WKV chunked scan ------------------------------------------
__global__ __launch_bounds__(256) void wkv_phase_a(
    const float* __restrict__ k, const float* __restrict__ v,
    const float* __restrict__ td, float* __restrict__ Ca, float* __restrict__ Cb)
{
    const int gid = blockIdx.x * blockDim.x + threadIdx.x;   // < NCH*B*C
    const int c  = gid & (Cq - 1);
    const int r  = gid >> 10;
    const int b  = r & (Bq - 1);
    const int ch = r >> 3;
    const float w  = -expf(td[c]);
    const float dw = expf(w);
    const size_t base = ((size_t)(b * Tq + ch * LCH)) * Cq + c;
    float sa = 0.f, sb = 0.f;
    #pragma unroll 4
    for (int i = 0; i < LCH; i++) {
        const float kt = k[base + (size_t)i * Cq];
        const float vt = v[base + (size_t)i * Cq];
        const float ek = __expf(kt);
        sa = fmaf(dw, sa, ek * vt);
        sb = fmaf(dw, sb, ek);
    }
    Ca[gid] = sa; Cb[gid] = sb;
}

__global__ __launch_bounds__(256) void wkv_scan(
    const float* __restrict__ td,
    const float* __restrict__ Ca, const float* __restrict__ Cb,
    float* __restrict__ Sa, float* __restrict__ Sb)
{
    const int sid = blockIdx.x * blockDim.x + threadIdx.x;   // < B*C
    const int c = sid & (Cq - 1);
    const float w  = -expf(td[c]);
    const float dL = expf((float)LCH * w);
    float sa = 0.f, sb = 0.f;
    #pragma unroll
    for (int ch = 0; ch < NCH; ch++) {
        const int idx = ch * (Bq * Cq) + sid;
        Sa[idx] = sa; Sb[idx] = sb;
        sa = fmaf(dL, sa, Ca[idx]);
        sb = fmaf(dL, sb, Cb[idx]);
    }
}

__global__ __launch_bounds__(256) void wkv_phase_b(
    const float* __restrict__ k, const float* __restrict__ v, const float* __restrict__ sr,
    const float* __restrict__ td, const float* __restrict__ tf,
    const float* __restrict__ Sa, const float* __restrict__ Sb, __half* __restrict__ out)
{
    const int gid = blockIdx.x * blockDim.x + threadIdx.x;
    const int c  = gid & (Cq - 1);
    const int r  = gid >> 10;
    const int b  = r & (Bq - 1);
    const int ch = r >> 3;
    const float w  = -expf(td[c]);
    const float dw = expf(w);
    const float eu = expf(tf[c]);
    float a = Sa[gid], bb = Sb[gid];
    const size_t base = ((size_t)(b * Tq + ch * LCH)) * Cq + c;
    #pragma unroll 4
    for (int i = 0; i < LCH; i++) {
        const size_t off = base + (size_t)i * Cq;
        const float kt = k[off];
        const float vt = v[off];
        const float ek = __expf(kt);
        const float euk = eu * ek;
        const float y = (a + euk * vt) / (bb + euk);
        out[off] = __float2half_rn(sr[off] * y);   // feeds Wo GEMM only
        a  = fmaf(dw, a,  ek * vt);
        bb = fmaf(dw, bb, ek);
    }
}

// ---------------- launch -----------------------------------------------------
extern "C" void kernel_launch(void* const* d_in, const int* in_sizes, int n_in,
                              void* d_out, int out_size)
{
    const float* x     = (const float*)d_in[0];
    const float* ln1_g = (const float*)d_in[1];
    const float* ln1_b = (const float*)d_in[2];
    const float* ln2_g = (const float*)d_in[3];
    const float* ln2_b = (const float*)d_in[4];
    const float* td    = (const float*)d_in[5];
    const float* tf    = (const float*)d_in[6];
    const float* tmk   = (const float*)d_in[7];
    const float* tmv   = (const float*)d_in[8];
    const float* tmr   = (const float*)d_in[9];
    const float* Wk    = (const float*)d_in[10];
    const float* Wv    = (const float*)d_in[11];
    const float* Wr    = (const float*)d_in[12];
    const float* Wo    = (const float*)d_in[13];
    const float* fmk   = (const float*)d_in[14];
    const float* fmr   = (const float*)d_in[15];
    const float* Fk    = (const float*)d_in[16];
    const float* Fr    = (const float*)d_in[17];
    const float* Fv    = (const float*)d_in[18];
    float* out = (float*)d_out;

    __half *xk, *xv, *xr, *fk, *fr, *rw, *kk, *wh;
    float *k, *v, *sr, *x1, *sg, *Ca, *Cb, *Sa, *Sb;
    cudaGetSymbolAddress((void**)&xk, g_xk);
    cudaGetSymbolAddress((void**)&xv, g_xv);
    cudaGetSymbolAddress((void**)&xr, g_xr);
    cudaGetSymbolAddress((void**)&fk, g_fk);
    cudaGetSymbolAddress((void**)&fr, g_fr);
    cudaGetSymbolAddress((void**)&rw, g_rw);
    cudaGetSymbolAddress((void**)&kk, g_kk);
    cudaGetSymbolAddress((void**)&wh, g_wh);
    cudaGetSymbolAddress((void**)&k,  g_k);
    cudaGetSymbolAddress((void**)&v,  g_v);
    cudaGetSymbolAddress((void**)&sr, g_sr);
    cudaGetSymbolAddress((void**)&x1, g_x1);
    cudaGetSymbolAddress((void**)&sg, g_sg);
    cudaGetSymbolAddress((void**)&Ca, g_Ca);
    cudaGetSymbolAddress((void**)&Cb, g_Cb);
    cudaGetSymbolAddress((void**)&Sa, g_Sa);
    cudaGetSymbolAddress((void**)&Sb, g_Sb);

    const size_t CC = (size_t)Cq * Cq;          // 1M
    const size_t HC = (size_t)HIDq * Cq;        // 4M
    __half* hWk = wh;
    __half* hWv = wh + CC;
    __half* hWr = wh + 2 * CC;
    __half* hWo = wh + 3 * CC;
    __half* hFr = wh + 4 * CC;
    __half* hFk = wh + 5 * CC;
    __half* hFv = wh + 5 * CC + HC;

    cudaFuncSetAttribute(gemm_f16<0>, cudaFuncAttributeMaxDynamicSharedMemorySize, GEMM_SMEM);
    cudaFuncSetAttribute(gemm_f16<1>, cudaFuncAttributeMaxDynamicSharedMemorySize, GEMM_SMEM);
    cudaFuncSetAttribute(gemm_f16<2>, cudaFuncAttributeMaxDynamicSharedMemorySize, GEMM_SMEM);
    cudaFuncSetAttribute(gemm_f16<3>, cudaFuncAttributeMaxDynamicSharedMemorySize, GEMM_SMEM);
    cudaFuncSetAttribute(gemm_f16<4>, cudaFuncAttributeMaxDynamicSharedMemorySize, GEMM_SMEM);
    cudaFuncSetAttribute(gemm_kv,     cudaFuncAttributeMaxDynamicSharedMemorySize, GEMM_SMEM);

    // 0,1: weight conversion
    w2h5<<<dim3((unsigned)(CC / 4 / 256), 5), 256>>>(Wk, Wv, Wr, Wo, Fr, wh);
    w2h2<<<dim3((unsigned)(HC / 4 / 256), 2), 256>>>(Fk, Fv, wh + 5 * CC);

    const dim3 gC (Cq / BN,  Mq / BM);       // (8, 128)      N=1024
    const dim3 gC2(Cq / BN,  Mq / BM, 2);    // (8, 128, 2)   k+v merged
    const dim3 gH (HIDq / BN, Mq / BM);      // (32, 128)     N=4096

    // att branch
    ln_mix<3><<<Mq, 256>>>(x, ln1_g, ln1_b, tmk, tmv, tmr, xk, xv, xr);        // 2
    gemm_kv<<<gC2, 128, GEMM_SMEM>>>(xk, xv, hWk, hWv, k, v, Cq, Cq);          // 3
    gemm_f16<1><<<gC, 128, GEMM_SMEM>>>(xr, hWr, sr, nullptr, nullptr, Cq, Cq); // 4

    wkv_phase_a<<<(NCH * Bq * Cq) / 256, 256>>>(k, v, td, Ca, Cb);             // 5 <- profiled
    wkv_scan   <<<(Bq * Cq) / 256, 256>>>(td, Ca, Cb, Sa, Sb);
    wkv_phase_b<<<(NCH * Bq * Cq) / 256, 256>>>(k, v, sr, td, tf, Sa, Sb, rw);

    gemm_f16<3><<<gC, 128, GEMM_SMEM>>>(rw, hWo, x1, x, nullptr, Cq, Cq);

    // ffn branch
    ln_mix<2><<<Mq, 256>>>(x1, ln2_g, ln2_b, fmk, fmr, nullptr, fk, fr, nullptr);
    gemm_f16<2><<<gH, 128, GEMM_SMEM>>>(fk, hFk, kk, nullptr, nullptr, HIDq, Cq);
    gemm_f16<1><<<gC, 128, GEMM_SMEM>>>(fr, hFr, sg, nullptr, nullptr, Cq, Cq);
    gemm_f16<4><<<gC, 128, GEMM_SMEM>>>(kk, hFv, out, x1, sg, Cq, HIDq);
}